// round 1
// baseline (speedup 1.0000x reference)
#include <cuda_runtime.h>
#include <cuda_bf16.h>

// Shapes (fixed for this problem)
#define S  2048   // sequence length
#define D  512    // model dim
#define KC 256    // q/k projection dim

// ---------------- scratch (allocation-free: __device__ globals) ----------------
__device__ float g_q[S * KC];      // q projections
__device__ float g_k[S * KC];      // k projections
__device__ float g_scores[(size_t)S * S];  // 16 MB score matrix
__device__ float g_v[S * D];       // v projections (block 2/3)
__device__ float g_h1[S * D];      // block-1 output
__device__ float g_h2[S * D];      // block-2 output
__device__ float g_qrow[KC];       // block-3 last-row query
__device__ float g_srow[S];        // block-3 score row

// ---------------- GEMM: C[M,N] = A[M,Kd] * op(B) + bias ----------------
// TRANSB=false: B is [Kd,N];  TRANSB=true: B is [N,Kd] (C = A * B^T)
// Tiles: 64x64x16, 256 threads, 4x4 register tile per thread. All dims are
// multiples of tile sizes for this problem, so no bounds checks.
#define BM 64
#define BN 64
#define BKT 16

template <bool TRANSB>
__global__ void __launch_bounds__(256) gemm_kernel(
    const float* __restrict__ A, const float* __restrict__ B,
    const float* __restrict__ bias, float* __restrict__ C,
    int M, int N, int Kd)
{
    __shared__ float As[BKT][BM];
    __shared__ float Bs[BKT][BN];

    const int t  = threadIdx.x;
    const int tx = t & 15;       // 0..15  -> N direction
    const int ty = t >> 4;       // 0..15  -> M direction
    const int m0 = blockIdx.y * BM;
    const int n0 = blockIdx.x * BN;

    float acc[4][4] = {};

    for (int k0 = 0; k0 < Kd; k0 += BKT) {
        // Load A tile (64x16) transposed into As[k][m]; one float4 per thread.
        {
            const int arow = t >> 2;          // 0..63
            const int ac   = (t & 3) * 4;     // 0,4,8,12
            float4 av = *reinterpret_cast<const float4*>(
                &A[(size_t)(m0 + arow) * Kd + k0 + ac]);
            As[ac + 0][arow] = av.x;
            As[ac + 1][arow] = av.y;
            As[ac + 2][arow] = av.z;
            As[ac + 3][arow] = av.w;
        }
        // Load B tile (16x64) into Bs[k][n]
        if (!TRANSB) {
            const int brow = t >> 4;          // 0..15
            const int bc   = (t & 15) * 4;    // 0..60
            *reinterpret_cast<float4*>(&Bs[brow][bc]) =
                *reinterpret_cast<const float4*>(
                    &B[(size_t)(k0 + brow) * N + n0 + bc]);
        } else {
            const int bcol = t >> 2;          // 0..63
            const int br   = (t & 3) * 4;     // 0,4,8,12
            float4 bv = *reinterpret_cast<const float4*>(
                &B[(size_t)(n0 + bcol) * Kd + k0 + br]);
            Bs[br + 0][bcol] = bv.x;
            Bs[br + 1][bcol] = bv.y;
            Bs[br + 2][bcol] = bv.z;
            Bs[br + 3][bcol] = bv.w;
        }
        __syncthreads();

        #pragma unroll
        for (int kk = 0; kk < BKT; kk++) {
            float4 a4 = *reinterpret_cast<const float4*>(&As[kk][ty * 4]);
            float4 b4 = *reinterpret_cast<const float4*>(&Bs[kk][tx * 4]);
            float ar[4] = {a4.x, a4.y, a4.z, a4.w};
            float br[4] = {b4.x, b4.y, b4.z, b4.w};
            #pragma unroll
            for (int i = 0; i < 4; i++)
                #pragma unroll
                for (int j = 0; j < 4; j++)
                    acc[i][j] = fmaf(ar[i], br[j], acc[i][j]);
        }
        __syncthreads();
    }

    float b0 = 0.f, b1 = 0.f, b2 = 0.f, b3 = 0.f;
    if (bias) {
        b0 = bias[n0 + tx * 4 + 0];
        b1 = bias[n0 + tx * 4 + 1];
        b2 = bias[n0 + tx * 4 + 2];
        b3 = bias[n0 + tx * 4 + 3];
    }
    #pragma unroll
    for (int i = 0; i < 4; i++) {
        const int m = m0 + ty * 4 + i;
        float4 o;
        o.x = acc[i][0] + b0;
        o.y = acc[i][1] + b1;
        o.z = acc[i][2] + b2;
        o.w = acc[i][3] + b3;
        *reinterpret_cast<float4*>(&C[(size_t)m * N + n0 + tx * 4]) = o;
    }
}

// ---------------- row-wise softmax (one block per row) ----------------
__global__ void softmax_rows(float* __restrict__ M, int cols)
{
    float* row = M + (size_t)blockIdx.x * cols;
    __shared__ float red[256];
    const int t = threadIdx.x;

    float m = -1e30f;
    for (int c = t; c < cols; c += 256) m = fmaxf(m, row[c]);
    red[t] = m; __syncthreads();
    for (int s = 128; s > 0; s >>= 1) {
        if (t < s) red[t] = fmaxf(red[t], red[t + s]);
        __syncthreads();
    }
    m = red[0]; __syncthreads();

    float sum = 0.f;
    for (int c = t; c < cols; c += 256) {
        float e = __expf(row[c] - m);
        row[c] = e;
        sum += e;
    }
    red[t] = sum; __syncthreads();
    for (int s = 128; s > 0; s >>= 1) {
        if (t < s) red[t] += red[t + s];
        __syncthreads();
    }
    const float inv = 1.0f / red[0];
    for (int c = t; c < cols; c += 256) row[c] *= inv;
}

// ---------------- row-wise L2 normalize (one block per row) ----------------
__global__ void l2norm_rows(float* __restrict__ V, int cols)
{
    float* row = V + (size_t)blockIdx.x * cols;
    __shared__ float red[128];
    const int t = threadIdx.x;

    float s = 0.f;
    for (int c = t; c < cols; c += 128) {
        float v = row[c];
        s += v * v;
    }
    red[t] = s; __syncthreads();
    for (int st = 64; st > 0; st >>= 1) {
        if (t < st) red[t] += red[t + st];
        __syncthreads();
    }
    const float inv = 1.0f / sqrtf(red[0]);
    for (int c = t; c < cols; c += 128) row[c] *= inv;
}

// ---------------- block-3 tiny kernels ----------------
// out[n] = h[:] . W[:,n] + b[n]   (single block, Nout threads)
__global__ void rowproj(const float* __restrict__ h, const float* __restrict__ W,
                        const float* __restrict__ b, float* __restrict__ out,
                        int Din, int Nout)
{
    const int n = threadIdx.x;
    if (n >= Nout) return;
    float s = b[n];
    for (int d = 0; d < Din; d++) s = fmaf(h[d], W[(size_t)d * Nout + n], s);
    out[n] = s;
}

// srow[j] = q . Kmat[j,:]   (one warp per j)
__global__ void dotrow(const float* __restrict__ q, const float* __restrict__ Kmat,
                       float* __restrict__ srow, int Kd)
{
    const int j = blockIdx.x;
    const int t = threadIdx.x;
    float s = 0.f;
    for (int c = t; c < Kd; c += 32)
        s = fmaf(q[c], Kmat[(size_t)j * Kd + c], s);
    #pragma unroll
    for (int o = 16; o > 0; o >>= 1) s += __shfl_down_sync(0xffffffffu, s, o);
    if (t == 0) srow[j] = s;
}

// out[d] = sum_j p[j] * V[j,d]
__global__ void av_row(const float* __restrict__ p, const float* __restrict__ V,
                       float* __restrict__ out, int rows, int cols)
{
    const int d = blockIdx.x * blockDim.x + threadIdx.x;
    if (d >= cols) return;
    float s = 0.f;
    for (int j = 0; j < rows; j++)
        s = fmaf(p[j], V[(size_t)j * cols + d], s);
    out[d] = s;
}

// ---------------- launch ----------------
extern "C" void kernel_launch(void* const* d_in, const int* in_sizes, int n_in,
                              void* d_out, int out_size)
{
    // metadata order: x, Wk1, bk1, Wq1, bq1, Wk2, bk2, Wq2, bq2, Wv2, bv2
    const float* x   = (const float*)d_in[0];   // [8, S, D] — only batch 0 used
    const float* Wk1 = (const float*)d_in[1];
    const float* bk1 = (const float*)d_in[2];
    const float* Wq1 = (const float*)d_in[3];
    const float* bq1 = (const float*)d_in[4];
    const float* Wk2 = (const float*)d_in[5];
    const float* bk2 = (const float*)d_in[6];
    const float* Wq2 = (const float*)d_in[7];
    const float* bq2 = (const float*)d_in[8];
    const float* Wv2 = (const float*)d_in[9];
    const float* bv2 = (const float*)d_in[10];
    float* out = (float*)d_out;                 // [D]

    float *q, *k, *sc, *v, *h1, *h2, *qrow, *srow;
    cudaGetSymbolAddress((void**)&q,    g_q);
    cudaGetSymbolAddress((void**)&k,    g_k);
    cudaGetSymbolAddress((void**)&sc,   g_scores);
    cudaGetSymbolAddress((void**)&v,    g_v);
    cudaGetSymbolAddress((void**)&h1,   g_h1);
    cudaGetSymbolAddress((void**)&h2,   g_h2);
    cudaGetSymbolAddress((void**)&qrow, g_qrow);
    cudaGetSymbolAddress((void**)&srow, g_srow);

    const dim3 gProj(KC / BN, S / BM);   // (4, 32)  M=S, N=KC, Kd=D
    const dim3 gScor(S  / BN, S / BM);   // (32, 32) M=S, N=S,  Kd=KC
    const dim3 gAV  (D  / BN, S / BM);   // (8, 32)  M=S, N=D,  Kd=S
    const dim3 gVPr (D  / BN, S / BM);   // (8, 32)  M=S, N=D,  Kd=D

    // ---------- Block 1 (values = x, batch 0 only) ----------
    gemm_kernel<false><<<gProj, 256>>>(x, Wq1, bq1, q, S, KC, D);
    gemm_kernel<false><<<gProj, 256>>>(x, Wk1, bk1, k, S, KC, D);
    gemm_kernel<true ><<<gScor, 256>>>(q, k, nullptr, sc, S, S, KC);
    softmax_rows<<<S, 256>>>(sc, S);
    gemm_kernel<false><<<gAV,  256>>>(sc, x, nullptr, h1, S, D, S);

    // ---------- Block 2 ----------
    gemm_kernel<false><<<gProj, 256>>>(h1, Wq2, bq2, q, S, KC, D);
    gemm_kernel<false><<<gProj, 256>>>(h1, Wk2, bk2, k, S, KC, D);
    gemm_kernel<false><<<gVPr,  256>>>(h1, Wv2, bv2, v, S, D, D);
    l2norm_rows<<<S, 128>>>(v, D);
    gemm_kernel<true ><<<gScor, 256>>>(q, k, nullptr, sc, S, S, KC);
    softmax_rows<<<S, 256>>>(sc, S);
    gemm_kernel<false><<<gAV,  256>>>(sc, v, nullptr, h2, S, D, S);

    // ---------- Block 3 (only the last query row is needed) ----------
    gemm_kernel<false><<<gProj, 256>>>(h2, Wk2, bk2, k, S, KC, D);
    gemm_kernel<false><<<gVPr,  256>>>(h2, Wv2, bv2, v, S, D, D);
    l2norm_rows<<<S, 128>>>(v, D);
    rowproj<<<1, KC>>>(h2 + (size_t)(S - 1) * D, Wq2, bq2, qrow, D, KC);
    dotrow<<<S, 32>>>(qrow, k, srow, KC);
    softmax_rows<<<1, 256>>>(srow, S);
    av_row<<<2, 256>>>(srow, v, out, S, D);
}

// round 4
// speedup vs baseline: 1.5983x; 1.5983x over previous
#include <cuda_runtime.h>
#include <cuda_fp16.h>
#include <cstdint>

// Shapes (fixed)
#define S  2048
#define D  512
#define KC 256

// ---------------- scratch ----------------
__device__ float g_q[S * KC];
__device__ float g_k[S * KC];
__device__ float g_scores[(size_t)S * S];
__device__ float g_v[S * D];
__device__ float g_h1[S * D];
__device__ float g_h2[S * D];
__device__ float g_qrow[KC];
__device__ float g_srow[S];

// ---------------- helpers ----------------
__device__ __forceinline__ uint32_t smem_u32(const void* p) {
    uint32_t a;
    asm("{ .reg .u64 t; cvta.to.shared.u64 t, %1; cvt.u32.u64 %0, t; }" : "=r"(a) : "l"(p));
    return a;
}
__device__ __forceinline__ void ldsm4(uint32_t* r, uint32_t a) {
    asm volatile("ldmatrix.sync.aligned.m8n8.x4.shared.b16 {%0,%1,%2,%3}, [%4];"
                 : "=r"(r[0]), "=r"(r[1]), "=r"(r[2]), "=r"(r[3]) : "r"(a));
}
__device__ __forceinline__ void mma_f16(float* c, const uint32_t* a, const uint32_t* b) {
    asm volatile(
        "mma.sync.aligned.m16n8k16.row.col.f32.f16.f16.f32 "
        "{%0,%1,%2,%3}, {%4,%5,%6,%7}, {%8,%9}, {%0,%1,%2,%3};"
        : "+f"(c[0]), "+f"(c[1]), "+f"(c[2]), "+f"(c[3])
        : "r"(a[0]), "r"(a[1]), "r"(a[2]), "r"(a[3]), "r"(b[0]), "r"(b[1]));
}
// split two floats into packed hi-half2 and lo-half2 (error-corrected fp16x2)
__device__ __forceinline__ void split2(float a, float b, uint32_t& hi, uint32_t& lo) {
    __half ha = __float2half_rn(a), hb = __float2half_rn(b);
    hi = ((uint32_t)__half_as_ushort(hb) << 16) | (uint32_t)__half_as_ushort(ha);
    float ra = a - __half2float(ha), rb = b - __half2float(hb);
    __half la = __float2half_rn(ra), lb = __float2half_rn(rb);
    lo = ((uint32_t)__half_as_ushort(lb) << 16) | (uint32_t)__half_as_ushort(la);
}

// ---------------- fp16x2-split tensor-core GEMM ----------------
// C[M,N] = A[M,K] * op(B) + bias.  TRANSB: B is [N,K] (C = A*B^T), else B is [K,N].
// SMEM rows are 80 bytes (32 data halfs + pad) -> conflict-free ldmatrix.
template <int BM, int BN, int WM, int WN, bool TRANSB>
__global__ void __launch_bounds__(WM* WN * 32, 1) mma_gemm(
    const float* __restrict__ A, const float* __restrict__ B,
    const float* __restrict__ bias, float* __restrict__ C,
    int M, int N, int K)
{
    constexpr int T = WM * WN * 32;
    constexpr int WTM = BM / WM, WTN = BN / WN;
    constexpr int MT = WTM / 16, NT = WTN / 8;
    constexpr int ROWB = 80;
    constexpr int ATILE = BM * ROWB;
    constexpr int BTILE = BN * ROWB;
    constexpr int STAGE = 2 * (ATILE + BTILE);
    constexpr int AV4 = (BM * 8) / T;   // float4 per thread for A per chunk
    constexpr int BV4 = (BN * 8) / T;

    extern __shared__ char smc[];
    const uint32_t sb0 = smem_u32(smc);
    const int t = threadIdx.x, lane = t & 31, wid = t >> 5;
    const int wm = (wid % WM) * WTM, wn = (wid / WM) * WTN;
    const int m0 = blockIdx.y * BM, n0 = blockIdx.x * BN;

    float acc[MT][NT][4];
    #pragma unroll
    for (int i = 0; i < MT; i++)
        #pragma unroll
        for (int j = 0; j < NT; j++)
            #pragma unroll
            for (int k = 0; k < 4; k++) acc[i][j][k] = 0.f;

    float4 abuf[AV4], bbuf[BV4];
    const int NC = K >> 5;

    auto ldg_chunk = [&](int k0) {
        #pragma unroll
        for (int i = 0; i < AV4; i++) {
            int v = t + i * T; int r = v >> 3, kq = v & 7;
            abuf[i] = *reinterpret_cast<const float4*>(&A[(size_t)(m0 + r) * K + k0 + kq * 4]);
        }
        #pragma unroll
        for (int i = 0; i < BV4; i++) {
            int v = t + i * T;
            if (TRANSB) {
                int r = v >> 3, kq = v & 7;
                bbuf[i] = *reinterpret_cast<const float4*>(&B[(size_t)(n0 + r) * K + k0 + kq * 4]);
            } else {
                int j = v & 3, rest = v >> 2;
                int nb = rest % (BN / 4), kq = rest / (BN / 4);
                bbuf[i] = *reinterpret_cast<const float4*>(&B[(size_t)(k0 + kq * 4 + j) * N + n0 + nb * 4]);
            }
        }
    };

    auto sts_chunk = [&](uint32_t st) {
        #pragma unroll
        for (int i = 0; i < AV4; i++) {
            int v = t + i * T; int r = v >> 3, kq = v & 7;
            uint32_t h0, l0, h1, l1;
            split2(abuf[i].x, abuf[i].y, h0, l0);
            split2(abuf[i].z, abuf[i].w, h1, l1);
            uint32_t addr = st + (uint32_t)(r * ROWB + kq * 8);
            asm volatile("st.shared.v2.b32 [%0], {%1,%2};" :: "r"(addr), "r"(h0), "r"(h1) : "memory");
            asm volatile("st.shared.v2.b32 [%0], {%1,%2};" :: "r"(addr + ATILE), "r"(l0), "r"(l1) : "memory");
        }
        uint32_t bst = st + 2 * ATILE;
        #pragma unroll
        for (int i = 0; i < BV4; i++) {
            float4 f = bbuf[i];
            int v = t + i * T;
            int r, kq;
            if (TRANSB) {
                r = v >> 3; kq = v & 7;
            } else {
                int j = v & 3, rest = v >> 2;
                int nb = rest % (BN / 4), kq8 = rest / (BN / 4);
                // 4x4 transpose within quad of lanes (j = lane&3)
                bool b0 = (j & 1) != 0, b1 = (j & 2) != 0;
                float t01 = __shfl_xor_sync(0xffffffffu, b0 ? f.x : f.y, 1);
                if (b0) f.x = t01; else f.y = t01;
                float t23 = __shfl_xor_sync(0xffffffffu, b0 ? f.z : f.w, 1);
                if (b0) f.z = t23; else f.w = t23;
                float u0 = __shfl_xor_sync(0xffffffffu, b1 ? f.x : f.z, 2);
                if (b1) f.x = u0; else f.z = u0;
                float u1 = __shfl_xor_sync(0xffffffffu, b1 ? f.y : f.w, 2);
                if (b1) f.y = u1; else f.w = u1;
                r = nb * 4 + j; kq = kq8;
            }
            uint32_t h0, l0, h1, l1;
            split2(f.x, f.y, h0, l0);
            split2(f.z, f.w, h1, l1);
            uint32_t addr = bst + (uint32_t)(r * ROWB + kq * 8);
            asm volatile("st.shared.v2.b32 [%0], {%1,%2};" :: "r"(addr), "r"(h0), "r"(h1) : "memory");
            asm volatile("st.shared.v2.b32 [%0], {%1,%2};" :: "r"(addr + BTILE), "r"(l0), "r"(l1) : "memory");
        }
    };

    auto mma_stage = [&](uint32_t st) {
        const int l7 = lane & 7, mt = lane >> 3;
        #pragma unroll
        for (int ks = 0; ks < 2; ks++) {
            uint32_t af_h[MT][4], af_l[MT][4];
            #pragma unroll
            for (int mi = 0; mi < MT; mi++) {
                uint32_t ra = st + (uint32_t)((wm + mi * 16 + l7 + ((mt & 1) << 3)) * ROWB
                                              + ks * 32 + ((mt >> 1) << 4));
                ldsm4(af_h[mi], ra);
                ldsm4(af_l[mi], ra + ATILE);
            }
            uint32_t bf_h[NT][2], bf_l[NT][2];
            #pragma unroll
            for (int np = 0; np < NT / 2; np++) {
                uint32_t rb = st + 2 * ATILE
                            + (uint32_t)((wn + np * 16 + ((mt >> 1) << 3) + l7) * ROWB
                                         + ks * 32 + ((mt & 1) << 4));
                uint32_t r4[4];
                ldsm4(r4, rb);
                bf_h[2 * np][0] = r4[0]; bf_h[2 * np][1] = r4[1];
                bf_h[2 * np + 1][0] = r4[2]; bf_h[2 * np + 1][1] = r4[3];
                ldsm4(r4, rb + BTILE);
                bf_l[2 * np][0] = r4[0]; bf_l[2 * np][1] = r4[1];
                bf_l[2 * np + 1][0] = r4[2]; bf_l[2 * np + 1][1] = r4[3];
            }
            #pragma unroll
            for (int mi = 0; mi < MT; mi++)
                #pragma unroll
                for (int ni = 0; ni < NT; ni++) {
                    mma_f16(acc[mi][ni], af_h[mi], bf_h[ni]);
                    mma_f16(acc[mi][ni], af_h[mi], bf_l[ni]);
                    mma_f16(acc[mi][ni], af_l[mi], bf_h[ni]);
                }
        }
    };

    ldg_chunk(0);
    sts_chunk(sb0);
    __syncthreads();
    for (int c = 0; c < NC; c++) {
        if (c + 1 < NC) ldg_chunk((c + 1) * 32);
        mma_stage(sb0 + (uint32_t)((c & 1) * STAGE));
        if (c + 1 < NC) sts_chunk(sb0 + (uint32_t)(((c + 1) & 1) * STAGE));
        __syncthreads();
    }

    // epilogue: direct STG (float2), bias added here
    const int g = lane >> 2, w2 = (lane & 3) * 2;
    #pragma unroll
    for (int ni = 0; ni < NT; ni++) {
        int col = n0 + wn + ni * 8 + w2;
        float b0v = 0.f, b1v = 0.f;
        if (bias) { b0v = bias[col]; b1v = bias[col + 1]; }
        #pragma unroll
        for (int mi = 0; mi < MT; mi++) {
            int row = m0 + wm + mi * 16 + g;
            float2 v0 = make_float2(acc[mi][ni][0] + b0v, acc[mi][ni][1] + b1v);
            float2 v1 = make_float2(acc[mi][ni][2] + b0v, acc[mi][ni][3] + b1v);
            *reinterpret_cast<float2*>(&C[(size_t)row * N + col]) = v0;
            *reinterpret_cast<float2*>(&C[(size_t)(row + 8) * N + col]) = v1;
        }
    }
}

// SMEM sizes
#define SMEM64  (2 * 2 * (64 * 80 + 64 * 80))     // 40960
#define SMEM128 (2 * 2 * (128 * 80 + 128 * 80))   // 81920

// ---------------- row-wise softmax ----------------
__global__ void softmax_rows(float* __restrict__ Mx, int cols)
{
    float* row = Mx + (size_t)blockIdx.x * cols;
    __shared__ float red[256];
    const int t = threadIdx.x;

    float m = -1e30f;
    for (int c = t; c < cols; c += 256) m = fmaxf(m, row[c]);
    red[t] = m; __syncthreads();
    for (int s = 128; s > 0; s >>= 1) {
        if (t < s) red[t] = fmaxf(red[t], red[t + s]);
        __syncthreads();
    }
    m = red[0]; __syncthreads();

    float sum = 0.f;
    for (int c = t; c < cols; c += 256) {
        float e = __expf(row[c] - m);
        row[c] = e;
        sum += e;
    }
    red[t] = sum; __syncthreads();
    for (int s = 128; s > 0; s >>= 1) {
        if (t < s) red[t] += red[t + s];
        __syncthreads();
    }
    const float inv = 1.0f / red[0];
    for (int c = t; c < cols; c += 256) row[c] *= inv;
}

// ---------------- row-wise L2 normalize ----------------
__global__ void l2norm_rows(float* __restrict__ V, int cols)
{
    float* row = V + (size_t)blockIdx.x * cols;
    __shared__ float red[128];
    const int t = threadIdx.x;

    float s = 0.f;
    for (int c = t; c < cols; c += 128) { float v = row[c]; s += v * v; }
    red[t] = s; __syncthreads();
    for (int st = 64; st > 0; st >>= 1) {
        if (t < st) red[t] += red[t + st];
        __syncthreads();
    }
    const float inv = 1.0f / sqrtf(red[0]);
    for (int c = t; c < cols; c += 128) row[c] *= inv;
}

// ---------------- block-3 tiny kernels ----------------
__global__ void rowproj(const float* __restrict__ h, const float* __restrict__ W,
                        const float* __restrict__ b, float* __restrict__ out,
                        int Din, int Nout)
{
    const int n = threadIdx.x;
    if (n >= Nout) return;
    float s = b[n];
    for (int d = 0; d < Din; d++) s = fmaf(h[d], W[(size_t)d * Nout + n], s);
    out[n] = s;
}

__global__ void dotrow(const float* __restrict__ q, const float* __restrict__ Kmat,
                       float* __restrict__ srow, int Kd)
{
    const int j = blockIdx.x;
    const int t = threadIdx.x;
    float s = 0.f;
    for (int c = t; c < Kd; c += 32) s = fmaf(q[c], Kmat[(size_t)j * Kd + c], s);
    #pragma unroll
    for (int o = 16; o > 0; o >>= 1) s += __shfl_down_sync(0xffffffffu, s, o);
    if (t == 0) srow[j] = s;
}

__global__ void av_row(const float* __restrict__ p, const float* __restrict__ V,
                       float* __restrict__ out, int rows, int cols)
{
    const int d = blockIdx.x * blockDim.x + threadIdx.x;
    if (d >= cols) return;
    float s = 0.f;
    for (int j = 0; j < rows; j++) s = fmaf(p[j], V[(size_t)j * cols + d], s);
    out[d] = s;
}

// ---------------- launch ----------------
extern "C" void kernel_launch(void* const* d_in, const int* in_sizes, int n_in,
                              void* d_out, int out_size)
{
    const float* x   = (const float*)d_in[0];   // [8,S,D] — batch 0 only
    const float* Wk1 = (const float*)d_in[1];
    const float* bk1 = (const float*)d_in[2];
    const float* Wq1 = (const float*)d_in[3];
    const float* bq1 = (const float*)d_in[4];
    const float* Wk2 = (const float*)d_in[5];
    const float* bk2 = (const float*)d_in[6];
    const float* Wq2 = (const float*)d_in[7];
    const float* bq2 = (const float*)d_in[8];
    const float* Wv2 = (const float*)d_in[9];
    const float* bv2 = (const float*)d_in[10];
    float* out = (float*)d_out;

    float *q, *k, *sc, *v, *h1, *h2, *qrow, *srow;
    cudaGetSymbolAddress((void**)&q,    g_q);
    cudaGetSymbolAddress((void**)&k,    g_k);
    cudaGetSymbolAddress((void**)&sc,   g_scores);
    cudaGetSymbolAddress((void**)&v,    g_v);
    cudaGetSymbolAddress((void**)&h1,   g_h1);
    cudaGetSymbolAddress((void**)&h2,   g_h2);
    cudaGetSymbolAddress((void**)&qrow, g_qrow);
    cudaGetSymbolAddress((void**)&srow, g_srow);

    cudaFuncSetAttribute((const void*)mma_gemm<64, 64, 2, 2, false>,
                         cudaFuncAttributeMaxDynamicSharedMemorySize, SMEM64);
    cudaFuncSetAttribute((const void*)mma_gemm<128, 128, 4, 2, true>,
                         cudaFuncAttributeMaxDynamicSharedMemorySize, SMEM128);

    const dim3 gProj(KC / 64, S / 64);   // (4, 32)
    const dim3 gScor(S / 128, S / 128);  // (16, 16)
    const dim3 gAV  (D / 64, S / 64);    // (8, 32)
    const dim3 gVPr (D / 64, S / 64);    // (8, 32)

    // ---------- Block 1 ----------
    mma_gemm<64, 64, 2, 2, false><<<gProj, 128, SMEM64>>>(x, Wq1, bq1, q, S, KC, D);
    mma_gemm<64, 64, 2, 2, false><<<gProj, 128, SMEM64>>>(x, Wk1, bk1, k, S, KC, D);
    mma_gemm<128, 128, 4, 2, true><<<gScor, 256, SMEM128>>>(q, k, nullptr, sc, S, S, KC);
    softmax_rows<<<S, 256>>>(sc, S);
    mma_gemm<64, 64, 2, 2, false><<<gAV, 128, SMEM64>>>(sc, x, nullptr, h1, S, D, S);

    // ---------- Block 2 ----------
    mma_gemm<64, 64, 2, 2, false><<<gProj, 128, SMEM64>>>(h1, Wq2, bq2, q, S, KC, D);
    mma_gemm<64, 64, 2, 2, false><<<gProj, 128, SMEM64>>>(h1, Wk2, bk2, k, S, KC, D);
    mma_gemm<64, 64, 2, 2, false><<<gVPr, 128, SMEM64>>>(h1, Wv2, bv2, v, S, D, D);
    l2norm_rows<<<S, 128>>>(v, D);
    mma_gemm<128, 128, 4, 2, true><<<gScor, 256, SMEM128>>>(q, k, nullptr, sc, S, S, KC);
    softmax_rows<<<S, 256>>>(sc, S);
    mma_gemm<64, 64, 2, 2, false><<<gAV, 128, SMEM64>>>(sc, v, nullptr, h2, S, D, S);

    // ---------- Block 3 (only last query row needed) ----------
    mma_gemm<64, 64, 2, 2, false><<<gProj, 128, SMEM64>>>(h2, Wk2, bk2, k, S, KC, D);
    mma_gemm<64, 64, 2, 2, false><<<gVPr, 128, SMEM64>>>(h2, Wv2, bv2, v, S, D, D);
    l2norm_rows<<<S, 128>>>(v, D);
    rowproj<<<1, KC>>>(h2 + (size_t)(S - 1) * D, Wq2, bq2, qrow, D, KC);
    dotrow<<<S, 32>>>(qrow, k, srow, KC);
    softmax_rows<<<1, 256>>>(srow, S);
    av_row<<<2, 256>>>(srow, v, out, S, D);
}

// round 5
// speedup vs baseline: 1.8861x; 1.1801x over previous
#include <cuda_runtime.h>
#include <cuda_fp16.h>
#include <cstdint>

// Shapes (fixed)
#define S  2048
#define D  512
#define KC 256

// ---------------- fp32 scratch ----------------
__device__ float g_scores[(size_t)S * S];
__device__ float g_v[S * D];
__device__ float g_h2[S * D];
__device__ float g_k3[S * KC];
__device__ float g_qrow[KC];
__device__ float g_srow[S];

// ---------------- fp16 hi/lo scratch (16B aligned for cp.async) ----------------
#define HBUF(name, n) __device__ __align__(16) __half name[n]
HBUF(g_xh,  S * D);  HBUF(g_xl,  S * D);
HBUF(g_xTh, D * S);  HBUF(g_xTl, D * S);
HBUF(g_wq1h, KC * D); HBUF(g_wq1l, KC * D);
HBUF(g_wk1h, KC * D); HBUF(g_wk1l, KC * D);
HBUF(g_wq2h, KC * D); HBUF(g_wq2l, KC * D);
HBUF(g_wk2h, KC * D); HBUF(g_wk2l, KC * D);
HBUF(g_wv2h, D * D);  HBUF(g_wv2l, D * D);
HBUF(g_qh, S * KC);  HBUF(g_ql, S * KC);
HBUF(g_kh, S * KC);  HBUF(g_kl, S * KC);
HBUF(g_ph, (size_t)S * S);  HBUF(g_pl, (size_t)S * S);
HBUF(g_h1h, S * D);  HBUF(g_h1l, S * D);
HBUF(g_vTh, D * S);  HBUF(g_vTl, D * S);
HBUF(g_h2h, S * D);  HBUF(g_h2l, S * D);

// ---------------- helpers ----------------
__device__ __forceinline__ uint32_t smem_u32(const void* p) {
    uint32_t a;
    asm("{ .reg .u64 t; cvta.to.shared.u64 t, %1; cvt.u32.u64 %0, t; }" : "=r"(a) : "l"(p));
    return a;
}
__device__ __forceinline__ void ldsm4(uint32_t* r, uint32_t a) {
    asm volatile("ldmatrix.sync.aligned.m8n8.x4.shared.b16 {%0,%1,%2,%3}, [%4];"
                 : "=r"(r[0]), "=r"(r[1]), "=r"(r[2]), "=r"(r[3]) : "r"(a));
}
__device__ __forceinline__ void mma_f16(float* c, const uint32_t* a, const uint32_t* b) {
    asm volatile(
        "mma.sync.aligned.m16n8k16.row.col.f32.f16.f16.f32 "
        "{%0,%1,%2,%3}, {%4,%5,%6,%7}, {%8,%9}, {%0,%1,%2,%3};"
        : "+f"(c[0]), "+f"(c[1]), "+f"(c[2]), "+f"(c[3])
        : "r"(a[0]), "r"(a[1]), "r"(a[2]), "r"(a[3]), "r"(b[0]), "r"(b[1]));
}
__device__ __forceinline__ void cp16(uint32_t dst, const void* src) {
    asm volatile("cp.async.cg.shared.global [%0], [%1], 16;" :: "r"(dst), "l"(src));
}
#define CP_COMMIT() asm volatile("cp.async.commit_group;" ::: "memory")
#define CP_WAIT1()  asm volatile("cp.async.wait_group 1;" ::: "memory")

__device__ __forceinline__ void split1(float v, __half& h, __half& l) {
    h = __float2half_rn(v);
    l = __float2half_rn(v - __half2float(h));
}

// ---------------- fp16 hi/lo split tensor-core GEMM ----------------
// C[M,N] = (Ah+Al)[M,K] * (Bh+Bl)[N,K]^T + bias.  All operands K-major fp16.
// OUT: 0 = fp32 C; 1 = fp16 Ch/Cl; 2 = both.
#define ROWB 80

template <int BM, int BN, int WM, int WN, int OUT>
__global__ void __launch_bounds__(WM* WN * 32, (BM == 64) ? 2 : 1) mma_gemm(
    const __half* __restrict__ Ah, const __half* __restrict__ Al,
    const __half* __restrict__ Bh, const __half* __restrict__ Bl,
    const float* __restrict__ bias,
    float* __restrict__ C, __half* __restrict__ Ch, __half* __restrict__ Cl,
    int M, int N, int K)
{
    constexpr int T = WM * WN * 32;
    constexpr int WTM = BM / WM, WTN = BN / WN;
    constexpr int MT = WTM / 16, NT = WTN / 8;
    constexpr int ATILE = BM * ROWB;
    constexpr int BTILE = BN * ROWB;
    constexpr int STAGE = 2 * ATILE + 2 * BTILE;

    extern __shared__ char smc[];
    const uint32_t sb0 = smem_u32(smc);
    const int t = threadIdx.x, lane = t & 31, wid = t >> 5;
    const int wm = (wid % WM) * WTM, wn = (wid / WM) * WTN;
    const int m0 = blockIdx.y * BM, n0 = blockIdx.x * BN;

    float acc[MT][NT][4];
    #pragma unroll
    for (int i = 0; i < MT; i++)
        #pragma unroll
        for (int j = 0; j < NT; j++)
            #pragma unroll
            for (int k = 0; k < 4; k++) acc[i][j][k] = 0.f;

    const int NC = K >> 5;

    auto cp_chunk = [&](uint32_t st, int k0) {
        #pragma unroll
        for (int i = 0; i < (BM * 4) / T; i++) {
            int v = t + i * T; int r = v >> 2, s = v & 3;
            uint32_t d = st + (uint32_t)(r * ROWB + s * 16);
            const size_t o = (size_t)(m0 + r) * K + k0 + s * 8;
            cp16(d, Ah + o);
            cp16(d + ATILE, Al + o);
        }
        #pragma unroll
        for (int i = 0; i < (BN * 4) / T; i++) {
            int v = t + i * T; int r = v >> 2, s = v & 3;
            uint32_t d = st + 2 * ATILE + (uint32_t)(r * ROWB + s * 16);
            const size_t o = (size_t)(n0 + r) * K + k0 + s * 8;
            cp16(d, Bh + o);
            cp16(d + BTILE, Bl + o);
        }
    };

    auto mma_stage = [&](uint32_t st) {
        const int l7 = lane & 7, mt = lane >> 3;
        #pragma unroll
        for (int ks = 0; ks < 2; ks++) {
            uint32_t af_h[MT][4], af_l[MT][4];
            #pragma unroll
            for (int mi = 0; mi < MT; mi++) {
                uint32_t ra = st + (uint32_t)((wm + mi * 16 + l7 + ((mt & 1) << 3)) * ROWB
                                              + ks * 32 + ((mt >> 1) << 4));
                ldsm4(af_h[mi], ra);
                ldsm4(af_l[mi], ra + ATILE);
            }
            uint32_t bf_h[NT][2], bf_l[NT][2];
            #pragma unroll
            for (int np = 0; np < NT / 2; np++) {
                uint32_t rb = st + 2 * ATILE
                            + (uint32_t)((wn + np * 16 + ((mt >> 1) << 3) + l7) * ROWB
                                         + ks * 32 + ((mt & 1) << 4));
                uint32_t r4[4];
                ldsm4(r4, rb);
                bf_h[2 * np][0] = r4[0]; bf_h[2 * np][1] = r4[1];
                bf_h[2 * np + 1][0] = r4[2]; bf_h[2 * np + 1][1] = r4[3];
                ldsm4(r4, rb + BTILE);
                bf_l[2 * np][0] = r4[0]; bf_l[2 * np][1] = r4[1];
                bf_l[2 * np + 1][0] = r4[2]; bf_l[2 * np + 1][1] = r4[3];
            }
            #pragma unroll
            for (int mi = 0; mi < MT; mi++)
                #pragma unroll
                for (int ni = 0; ni < NT; ni++) {
                    mma_f16(acc[mi][ni], af_h[mi], bf_h[ni]);
                    mma_f16(acc[mi][ni], af_h[mi], bf_l[ni]);
                    mma_f16(acc[mi][ni], af_l[mi], bf_h[ni]);
                }
        }
    };

    // 3-stage cp.async pipeline
    cp_chunk(sb0, 0);
    CP_COMMIT();
    if (NC > 1) cp_chunk(sb0 + STAGE, 32);
    CP_COMMIT();
    for (int c = 0; c < NC; c++) {
        CP_WAIT1();
        __syncthreads();
        mma_stage(sb0 + (uint32_t)((c % 3) * STAGE));
        __syncthreads();
        if (c + 2 < NC) cp_chunk(sb0 + (uint32_t)(((c + 2) % 3) * STAGE), (c + 2) * 32);
        CP_COMMIT();
    }

    // epilogue
    const int g = lane >> 2, w2 = (lane & 3) * 2;
    #pragma unroll
    for (int ni = 0; ni < NT; ni++) {
        const int col = n0 + wn + ni * 8 + w2;
        float b0v = 0.f, b1v = 0.f;
        if (bias) { b0v = bias[col]; b1v = bias[col + 1]; }
        #pragma unroll
        for (int mi = 0; mi < MT; mi++) {
            const int row = m0 + wm + mi * 16 + g;
            float c00 = acc[mi][ni][0] + b0v, c01 = acc[mi][ni][1] + b1v;
            float c10 = acc[mi][ni][2] + b0v, c11 = acc[mi][ni][3] + b1v;
            if (OUT == 0 || OUT == 2) {
                *reinterpret_cast<float2*>(&C[(size_t)row * N + col]) = make_float2(c00, c01);
                *reinterpret_cast<float2*>(&C[(size_t)(row + 8) * N + col]) = make_float2(c10, c11);
            }
            if (OUT >= 1) {
                __half h0, l0, h1, l1;
                split1(c00, h0, l0); split1(c01, h1, l1);
                *reinterpret_cast<__half2*>(&Ch[(size_t)row * N + col]) = __halves2half2(h0, h1);
                *reinterpret_cast<__half2*>(&Cl[(size_t)row * N + col]) = __halves2half2(l0, l1);
                split1(c10, h0, l0); split1(c11, h1, l1);
                *reinterpret_cast<__half2*>(&Ch[(size_t)(row + 8) * N + col]) = __halves2half2(h0, h1);
                *reinterpret_cast<__half2*>(&Cl[(size_t)(row + 8) * N + col]) = __halves2half2(l0, l1);
            }
        }
    }
}

#define SMEM64  (3 * (2 * 64 * ROWB + 2 * 64 * ROWB))      // 61440
#define SMEM128 (3 * (2 * 128 * ROWB + 2 * 128 * ROWB))    // 122880

// ---------------- converts ----------------
__global__ void cvt_split(const float* __restrict__ in, __half* __restrict__ oh,
                          __half* __restrict__ ol, int n)
{
    int i = (blockIdx.x * 256 + threadIdx.x) * 4;
    if (i >= n) return;
    float4 v = *reinterpret_cast<const float4*>(in + i);
    __half h0, l0, h1, l1, h2, l2, h3, l3;
    split1(v.x, h0, l0); split1(v.y, h1, l1); split1(v.z, h2, l2); split1(v.w, h3, l3);
    *reinterpret_cast<__half2*>(oh + i)     = __halves2half2(h0, h1);
    *reinterpret_cast<__half2*>(oh + i + 2) = __halves2half2(h2, h3);
    *reinterpret_cast<__half2*>(ol + i)     = __halves2half2(l0, l1);
    *reinterpret_cast<__half2*>(ol + i + 2) = __halves2half2(l2, l3);
}

// in [R,C] fp32 -> oh/ol [C,R] fp16 (transposed)
__global__ void cvt_split_T(const float* __restrict__ in, __half* __restrict__ oh,
                            __half* __restrict__ ol, int R, int C)
{
    __shared__ float tile[32][33];
    const int c0 = blockIdx.x * 32, r0 = blockIdx.y * 32;
    const int tx = threadIdx.x, ty = threadIdx.y;
    #pragma unroll
    for (int i = 0; i < 32; i += 8)
        tile[ty + i][tx] = in[(size_t)(r0 + ty + i) * C + c0 + tx];
    __syncthreads();
    #pragma unroll
    for (int i = 0; i < 32; i += 8) {
        float v = tile[tx][ty + i];
        __half h, l;
        split1(v, h, l);
        const size_t o = (size_t)(c0 + ty + i) * R + r0 + tx;
        oh[o] = h;
        ol[o] = l;
    }
}

// ---------------- register-resident softmax + fp16 split output ----------------
__global__ void softmax_cvt(const float* __restrict__ Sc, __half* __restrict__ Ph,
                            __half* __restrict__ Pl)
{
    const size_t base = (size_t)blockIdx.x * S;
    const int t = threadIdx.x, lane = t & 31, wid = t >> 5;
    __shared__ float red[8];

    float4 v0 = *reinterpret_cast<const float4*>(Sc + base + t * 4);
    float4 v1 = *reinterpret_cast<const float4*>(Sc + base + 1024 + t * 4);
    float m = fmaxf(fmaxf(fmaxf(v0.x, v0.y), fmaxf(v0.z, v0.w)),
                    fmaxf(fmaxf(v1.x, v1.y), fmaxf(v1.z, v1.w)));
    #pragma unroll
    for (int o = 16; o > 0; o >>= 1) m = fmaxf(m, __shfl_xor_sync(0xffffffffu, m, o));
    if (lane == 0) red[wid] = m;
    __syncthreads();
    m = red[0];
    #pragma unroll
    for (int i = 1; i < 8; i++) m = fmaxf(m, red[i]);
    __syncthreads();

    float e[8];
    e[0] = __expf(v0.x - m); e[1] = __expf(v0.y - m);
    e[2] = __expf(v0.z - m); e[3] = __expf(v0.w - m);
    e[4] = __expf(v1.x - m); e[5] = __expf(v1.y - m);
    e[6] = __expf(v1.z - m); e[7] = __expf(v1.w - m);
    float s = e[0] + e[1] + e[2] + e[3] + e[4] + e[5] + e[6] + e[7];
    #pragma unroll
    for (int o = 16; o > 0; o >>= 1) s += __shfl_xor_sync(0xffffffffu, s, o);
    if (lane == 0) red[wid] = s;
    __syncthreads();
    s = red[0];
    #pragma unroll
    for (int i = 1; i < 8; i++) s += red[i];
    const float inv = 1.0f / s;

    #pragma unroll
    for (int half = 0; half < 2; half++) {
        const size_t o = base + half * 1024 + t * 4;
        __half h0, l0, h1, l1, h2, l2, h3, l3;
        split1(e[half * 4 + 0] * inv, h0, l0);
        split1(e[half * 4 + 1] * inv, h1, l1);
        split1(e[half * 4 + 2] * inv, h2, l2);
        split1(e[half * 4 + 3] * inv, h3, l3);
        *reinterpret_cast<__half2*>(Ph + o)     = __halves2half2(h0, h1);
        *reinterpret_cast<__half2*>(Ph + o + 2) = __halves2half2(h2, h3);
        *reinterpret_cast<__half2*>(Pl + o)     = __halves2half2(l0, l1);
        *reinterpret_cast<__half2*>(Pl + o + 2) = __halves2half2(l2, l3);
    }
}

// ---------------- fp32 softmax (1 small row) ----------------
__global__ void softmax_rows(float* __restrict__ Mx, int cols)
{
    float* row = Mx + (size_t)blockIdx.x * cols;
    __shared__ float red[256];
    const int t = threadIdx.x;
    float m = -1e30f;
    for (int c = t; c < cols; c += 256) m = fmaxf(m, row[c]);
    red[t] = m; __syncthreads();
    for (int s = 128; s > 0; s >>= 1) { if (t < s) red[t] = fmaxf(red[t], red[t + s]); __syncthreads(); }
    m = red[0]; __syncthreads();
    float sum = 0.f;
    for (int c = t; c < cols; c += 256) { float e = __expf(row[c] - m); row[c] = e; sum += e; }
    red[t] = sum; __syncthreads();
    for (int s = 128; s > 0; s >>= 1) { if (t < s) red[t] += red[t + s]; __syncthreads(); }
    const float inv = 1.0f / red[0];
    for (int c = t; c < cols; c += 256) row[c] *= inv;
}

// ---------------- row-wise L2 normalize (fp32 in place) ----------------
__global__ void l2norm_rows(float* __restrict__ V, int cols)
{
    float* row = V + (size_t)blockIdx.x * cols;
    __shared__ float red[128];
    const int t = threadIdx.x;
    float s = 0.f;
    for (int c = t; c < cols; c += 128) { float v = row[c]; s += v * v; }
    red[t] = s; __syncthreads();
    for (int st = 64; st > 0; st >>= 1) { if (t < st) red[t] += red[t + st]; __syncthreads(); }
    const float inv = 1.0f / sqrtf(red[0]);
    for (int c = t; c < cols; c += 128) row[c] *= inv;
}

// ---------------- block-3 tiny kernels ----------------
__global__ void rowproj(const float* __restrict__ h, const float* __restrict__ W,
                        const float* __restrict__ b, float* __restrict__ out,
                        int Din, int Nout)
{
    const int n = threadIdx.x;
    if (n >= Nout) return;
    float s = b[n];
    for (int d = 0; d < Din; d++) s = fmaf(h[d], W[(size_t)d * Nout + n], s);
    out[n] = s;
}

__global__ void dotrow(const float* __restrict__ q, const float* __restrict__ Kmat,
                       float* __restrict__ srow, int Kd)
{
    const int j = blockIdx.x;
    const int t = threadIdx.x;
    float s = 0.f;
    for (int c = t; c < Kd; c += 32) s = fmaf(q[c], Kmat[(size_t)j * Kd + c], s);
    #pragma unroll
    for (int o = 16; o > 0; o >>= 1) s += __shfl_down_sync(0xffffffffu, s, o);
    if (t == 0) srow[j] = s;
}

__global__ void av_row(const float* __restrict__ p, const float* __restrict__ V,
                       float* __restrict__ out, int rows, int cols)
{
    const int d = blockIdx.x * blockDim.x + threadIdx.x;
    if (d >= cols) return;
    float s = 0.f;
    for (int j = 0; j < rows; j++) s = fmaf(p[j], V[(size_t)j * cols + d], s);
    out[d] = s;
}

// ---------------- launch ----------------
extern "C" void kernel_launch(void* const* d_in, const int* in_sizes, int n_in,
                              void* d_out, int out_size)
{
    const float* x   = (const float*)d_in[0];   // [8,S,D] — batch 0 only
    const float* Wk1 = (const float*)d_in[1];
    const float* bk1 = (const float*)d_in[2];
    const float* Wq1 = (const float*)d_in[3];
    const float* bq1 = (const float*)d_in[4];
    const float* Wk2 = (const float*)d_in[5];
    const float* bk2 = (const float*)d_in[6];
    const float* Wq2 = (const float*)d_in[7];
    const float* bq2 = (const float*)d_in[8];
    const float* Wv2 = (const float*)d_in[9];
    const float* bv2 = (const float*)d_in[10];
    float* out = (float*)d_out;

    float *sc, *v, *h2, *k3, *qrow, *srow;
    cudaGetSymbolAddress((void**)&sc,   g_scores);
    cudaGetSymbolAddress((void**)&v,    g_v);
    cudaGetSymbolAddress((void**)&h2,   g_h2);
    cudaGetSymbolAddress((void**)&k3,   g_k3);
    cudaGetSymbolAddress((void**)&qrow, g_qrow);
    cudaGetSymbolAddress((void**)&srow, g_srow);

    __half *xh, *xl, *xTh, *xTl, *wq1h, *wq1l, *wk1h, *wk1l;
    __half *wq2h, *wq2l, *wk2h, *wk2l, *wv2h, *wv2l;
    __half *qh, *ql, *kh, *kl, *ph, *pl, *h1h, *h1l, *vTh, *vTl, *h2h, *h2l;
    cudaGetSymbolAddress((void**)&xh, g_xh);   cudaGetSymbolAddress((void**)&xl, g_xl);
    cudaGetSymbolAddress((void**)&xTh, g_xTh); cudaGetSymbolAddress((void**)&xTl, g_xTl);
    cudaGetSymbolAddress((void**)&wq1h, g_wq1h); cudaGetSymbolAddress((void**)&wq1l, g_wq1l);
    cudaGetSymbolAddress((void**)&wk1h, g_wk1h); cudaGetSymbolAddress((void**)&wk1l, g_wk1l);
    cudaGetSymbolAddress((void**)&wq2h, g_wq2h); cudaGetSymbolAddress((void**)&wq2l, g_wq2l);
    cudaGetSymbolAddress((void**)&wk2h, g_wk2h); cudaGetSymbolAddress((void**)&wk2l, g_wk2l);
    cudaGetSymbolAddress((void**)&wv2h, g_wv2h); cudaGetSymbolAddress((void**)&wv2l, g_wv2l);
    cudaGetSymbolAddress((void**)&qh, g_qh); cudaGetSymbolAddress((void**)&ql, g_ql);
    cudaGetSymbolAddress((void**)&kh, g_kh); cudaGetSymbolAddress((void**)&kl, g_kl);
    cudaGetSymbolAddress((void**)&ph, g_ph); cudaGetSymbolAddress((void**)&pl, g_pl);
    cudaGetSymbolAddress((void**)&h1h, g_h1h); cudaGetSymbolAddress((void**)&h1l, g_h1l);
    cudaGetSymbolAddress((void**)&vTh, g_vTh); cudaGetSymbolAddress((void**)&vTl, g_vTl);
    cudaGetSymbolAddress((void**)&h2h, g_h2h); cudaGetSymbolAddress((void**)&h2l, g_h2l);

    cudaFuncSetAttribute((const void*)mma_gemm<64, 64, 2, 2, 0>,
                         cudaFuncAttributeMaxDynamicSharedMemorySize, SMEM64);
    cudaFuncSetAttribute((const void*)mma_gemm<64, 64, 2, 2, 1>,
                         cudaFuncAttributeMaxDynamicSharedMemorySize, SMEM64);
    cudaFuncSetAttribute((const void*)mma_gemm<64, 64, 2, 2, 2>,
                         cudaFuncAttributeMaxDynamicSharedMemorySize, SMEM64);
    cudaFuncSetAttribute((const void*)mma_gemm<128, 128, 4, 2, 0>,
                         cudaFuncAttributeMaxDynamicSharedMemorySize, SMEM128);

    const dim3 gProj(KC / 64, S / 64);   // (4, 32)
    const dim3 gScor(S / 128, S / 128);  // (16, 16)
    const dim3 gAV  (D / 64, S / 64);    // (8, 32)
    const dim3 tT(32, 8);

    // ---------- converts (once per replay) ----------
    cvt_split<<<(S * D) / 1024, 256>>>(x, xh, xl, S * D);
    cvt_split_T<<<dim3(D / 32, S / 32), tT>>>(x, xTh, xTl, S, D);       // x[S,D] -> xT[D,S]
    cvt_split_T<<<dim3(KC / 32, D / 32), tT>>>(Wq1, wq1h, wq1l, D, KC); // W[D,KC] -> [KC,D]
    cvt_split_T<<<dim3(KC / 32, D / 32), tT>>>(Wk1, wk1h, wk1l, D, KC);
    cvt_split_T<<<dim3(KC / 32, D / 32), tT>>>(Wq2, wq2h, wq2l, D, KC);
    cvt_split_T<<<dim3(KC / 32, D / 32), tT>>>(Wk2, wk2h, wk2l, D, KC);
    cvt_split_T<<<dim3(D / 32, D / 32), tT>>>(Wv2, wv2h, wv2l, D, D);

    // ---------- Block 1 ----------
    mma_gemm<64, 64, 2, 2, 1><<<gProj, 128, SMEM64>>>(xh, xl, wq1h, wq1l, bq1, nullptr, qh, ql, S, KC, D);
    mma_gemm<64, 64, 2, 2, 1><<<gProj, 128, SMEM64>>>(xh, xl, wk1h, wk1l, bk1, nullptr, kh, kl, S, KC, D);
    mma_gemm<128, 128, 4, 2, 0><<<gScor, 256, SMEM128>>>(qh, ql, kh, kl, nullptr, sc, nullptr, nullptr, S, S, KC);
    softmax_cvt<<<S, 256>>>(sc, ph, pl);
    mma_gemm<64, 64, 2, 2, 1><<<gAV, 128, SMEM64>>>(ph, pl, xTh, xTl, nullptr, nullptr, h1h, h1l, S, D, S);

    // ---------- Block 2 ----------
    mma_gemm<64, 64, 2, 2, 1><<<gProj, 128, SMEM64>>>(h1h, h1l, wq2h, wq2l, bq2, nullptr, qh, ql, S, KC, D);
    mma_gemm<64, 64, 2, 2, 1><<<gProj, 128, SMEM64>>>(h1h, h1l, wk2h, wk2l, bk2, nullptr, kh, kl, S, KC, D);
    mma_gemm<64, 64, 2, 2, 0><<<gAV, 128, SMEM64>>>(h1h, h1l, wv2h, wv2l, bv2, v, nullptr, nullptr, S, D, D);
    l2norm_rows<<<S, 128>>>(v, D);
    cvt_split_T<<<dim3(D / 32, S / 32), tT>>>(v, vTh, vTl, S, D);       // v[S,D] -> vT[D,S]
    mma_gemm<128, 128, 4, 2, 0><<<gScor, 256, SMEM128>>>(qh, ql, kh, kl, nullptr, sc, nullptr, nullptr, S, S, KC);
    softmax_cvt<<<S, 256>>>(sc, ph, pl);
    mma_gemm<64, 64, 2, 2, 2><<<gAV, 128, SMEM64>>>(ph, pl, vTh, vTl, nullptr, h2, h2h, h2l, S, D, S);

    // ---------- Block 3 (only last query row needed) ----------
    mma_gemm<64, 64, 2, 2, 0><<<gProj, 128, SMEM64>>>(h2h, h2l, wk2h, wk2l, bk2, k3, nullptr, nullptr, S, KC, D);
    mma_gemm<64, 64, 2, 2, 0><<<gAV, 128, SMEM64>>>(h2h, h2l, wv2h, wv2l, bv2, v, nullptr, nullptr, S, D, D);
    l2norm_rows<<<S, 128>>>(v, D);
    rowproj<<<1, KC>>>(h2 + (size_t)(S - 1) * D, Wq2, bq2, qrow, D, KC);
    dotrow<<<S, 32>>>(qrow, k3, srow, KC);
    softmax_rows<<<1, 256>>>(srow, S);
    av_row<<<2, 256>>>(srow, v, out, S, D);
}

// round 6
// speedup vs baseline: 2.5026x; 1.3268x over previous
#include <cuda_runtime.h>
#include <cuda_fp16.h>
#include <cstdint>

// Shapes (fixed)
#define S  2048
#define D  512
#define KC 256

// ---------------- fp32 scratch ----------------
__device__ float g_sc[(size_t)S * S];       // scores
__device__ float g_qkv32[S * 1024];         // packed q|k|v fp32 (blocks 2/3)
__device__ float g_h2[S * D];               // block-2 output fp32
__device__ float g_qrow[KC];
__device__ float g_srow[S];

// ---------------- fp16 hi/lo scratch (16B aligned) ----------------
#define HBUF(name, n) __device__ __align__(16) __half name[n]
HBUF(g_xh,  S * D);   HBUF(g_xl,  S * D);
HBUF(g_xTh, D * S);   HBUF(g_xTl, D * S);
HBUF(g_wqk1h, 512 * D);  HBUF(g_wqk1l, 512 * D);     // [Wq1;Wk1] K-major
HBUF(g_wqkv2h, 1024 * D); HBUF(g_wqkv2l, 1024 * D);  // [Wq2;Wk2;Wv2] K-major
HBUF(g_qk1h, S * 512);  HBUF(g_qk1l, S * 512);
HBUF(g_qkvh, S * 1024); HBUF(g_qkvl, S * 1024);
HBUF(g_ph, (size_t)S * S);  HBUF(g_pl, (size_t)S * S);
HBUF(g_h1h, S * D);  HBUF(g_h1l, S * D);
HBUF(g_vTh, D * S);  HBUF(g_vTl, D * S);
HBUF(g_h2h, S * D);  HBUF(g_h2l, S * D);
__device__ float g_bqk1[512];
__device__ float g_bqkv2[1024];

// ---------------- helpers ----------------
__device__ __forceinline__ uint32_t smem_u32(const void* p) {
    uint32_t a;
    asm("{ .reg .u64 t; cvta.to.shared.u64 t, %1; cvt.u32.u64 %0, t; }" : "=r"(a) : "l"(p));
    return a;
}
__device__ __forceinline__ void ldsm4(uint32_t* r, uint32_t a) {
    asm volatile("ldmatrix.sync.aligned.m8n8.x4.shared.b16 {%0,%1,%2,%3}, [%4];"
                 : "=r"(r[0]), "=r"(r[1]), "=r"(r[2]), "=r"(r[3]) : "r"(a));
}
__device__ __forceinline__ void mma_f16(float* c, const uint32_t* a, const uint32_t* b) {
    asm volatile(
        "mma.sync.aligned.m16n8k16.row.col.f32.f16.f16.f32 "
        "{%0,%1,%2,%3}, {%4,%5,%6,%7}, {%8,%9}, {%0,%1,%2,%3};"
        : "+f"(c[0]), "+f"(c[1]), "+f"(c[2]), "+f"(c[3])
        : "r"(a[0]), "r"(a[1]), "r"(a[2]), "r"(a[3]), "r"(b[0]), "r"(b[1]));
}
__device__ __forceinline__ void cp16(uint32_t dst, const void* src) {
    asm volatile("cp.async.cg.shared.global [%0], [%1], 16;" :: "r"(dst), "l"(src));
}
#define CP_COMMIT() asm volatile("cp.async.commit_group;" ::: "memory")
#define CP_WAIT1()  asm volatile("cp.async.wait_group 1;" ::: "memory")

__device__ __forceinline__ void split1(float v, __half& h, __half& l) {
    h = __float2half_rn(v);
    l = __float2half_rn(v - __half2float(h));
}

// ---------------- fp16 hi/lo split tensor-core GEMM ----------------
// C[M,N] = (Ah+Al)[M,K] * (Bh+Bl)[N,K]^T + bias.  K-major fp16 operands.
// lda/ldb = row strides (elements) of A/B; ldc of outputs.
// OUT: 0 = fp32 C; 1 = fp16 Ch/Cl; 2 = both.
#define ROWB 80

template <int BM, int BN, int WM, int WN, int OUT>
__global__ void __launch_bounds__(WM* WN * 32, (BM == 64) ? 3 : 1) mma_gemm(
    const __half* __restrict__ Ah, const __half* __restrict__ Al,
    const __half* __restrict__ Bh, const __half* __restrict__ Bl,
    const float* __restrict__ bias,
    float* __restrict__ C, __half* __restrict__ Ch, __half* __restrict__ Cl,
    int K, int lda, int ldb, int ldc)
{
    constexpr int T = WM * WN * 32;
    constexpr int WTM = BM / WM, WTN = BN / WN;
    constexpr int MT = WTM / 16, NT = WTN / 8;
    constexpr int ATILE = BM * ROWB;
    constexpr int BTILE = BN * ROWB;
    constexpr int STAGE = 2 * ATILE + 2 * BTILE;

    extern __shared__ char smc[];
    const uint32_t sb0 = smem_u32(smc);
    const int t = threadIdx.x, lane = t & 31, wid = t >> 5;
    const int wm = (wid % WM) * WTM, wn = (wid / WM) * WTN;
    const int m0 = blockIdx.y * BM, n0 = blockIdx.x * BN;

    float acc[MT][NT][4];
    #pragma unroll
    for (int i = 0; i < MT; i++)
        #pragma unroll
        for (int j = 0; j < NT; j++)
            #pragma unroll
            for (int k = 0; k < 4; k++) acc[i][j][k] = 0.f;

    const int NC = K >> 5;

    auto cp_chunk = [&](uint32_t st, int k0) {
        #pragma unroll
        for (int i = 0; i < (BM * 4) / T; i++) {
            int v = t + i * T; int r = v >> 2, s = v & 3;
            uint32_t d = st + (uint32_t)(r * ROWB + s * 16);
            const size_t o = (size_t)(m0 + r) * lda + k0 + s * 8;
            cp16(d, Ah + o);
            cp16(d + ATILE, Al + o);
        }
        #pragma unroll
        for (int i = 0; i < (BN * 4) / T; i++) {
            int v = t + i * T; int r = v >> 2, s = v & 3;
            uint32_t d = st + 2 * ATILE + (uint32_t)(r * ROWB + s * 16);
            const size_t o = (size_t)(n0 + r) * ldb + k0 + s * 8;
            cp16(d, Bh + o);
            cp16(d + BTILE, Bl + o);
        }
    };

    auto mma_stage = [&](uint32_t st) {
        const int l7 = lane & 7, mt = lane >> 3;
        #pragma unroll
        for (int ks = 0; ks < 2; ks++) {
            uint32_t af_h[MT][4], af_l[MT][4];
            #pragma unroll
            for (int mi = 0; mi < MT; mi++) {
                uint32_t ra = st + (uint32_t)((wm + mi * 16 + l7 + ((mt & 1) << 3)) * ROWB
                                              + ks * 32 + ((mt >> 1) << 4));
                ldsm4(af_h[mi], ra);
                ldsm4(af_l[mi], ra + ATILE);
            }
            uint32_t bf_h[NT][2], bf_l[NT][2];
            #pragma unroll
            for (int np = 0; np < NT / 2; np++) {
                uint32_t rb = st + 2 * ATILE
                            + (uint32_t)((wn + np * 16 + ((mt >> 1) << 3) + l7) * ROWB
                                         + ks * 32 + ((mt & 1) << 4));
                uint32_t r4[4];
                ldsm4(r4, rb);
                bf_h[2 * np][0] = r4[0]; bf_h[2 * np][1] = r4[1];
                bf_h[2 * np + 1][0] = r4[2]; bf_h[2 * np + 1][1] = r4[3];
                ldsm4(r4, rb + BTILE);
                bf_l[2 * np][0] = r4[0]; bf_l[2 * np][1] = r4[1];
                bf_l[2 * np + 1][0] = r4[2]; bf_l[2 * np + 1][1] = r4[3];
            }
            #pragma unroll
            for (int mi = 0; mi < MT; mi++)
                #pragma unroll
                for (int ni = 0; ni < NT; ni++) {
                    mma_f16(acc[mi][ni], af_h[mi], bf_h[ni]);
                    mma_f16(acc[mi][ni], af_h[mi], bf_l[ni]);
                    mma_f16(acc[mi][ni], af_l[mi], bf_h[ni]);
                }
        }
    };

    cp_chunk(sb0, 0);
    CP_COMMIT();
    if (NC > 1) cp_chunk(sb0 + STAGE, 32);
    CP_COMMIT();
    for (int c = 0; c < NC; c++) {
        CP_WAIT1();
        __syncthreads();
        mma_stage(sb0 + (uint32_t)((c % 3) * STAGE));
        __syncthreads();
        if (c + 2 < NC) cp_chunk(sb0 + (uint32_t)(((c + 2) % 3) * STAGE), (c + 2) * 32);
        CP_COMMIT();
    }

    // epilogue
    const int g = lane >> 2, w2 = (lane & 3) * 2;
    #pragma unroll
    for (int ni = 0; ni < NT; ni++) {
        const int col = n0 + wn + ni * 8 + w2;
        float b0v = 0.f, b1v = 0.f;
        if (bias) { b0v = bias[col]; b1v = bias[col + 1]; }
        #pragma unroll
        for (int mi = 0; mi < MT; mi++) {
            const int row = m0 + wm + mi * 16 + g;
            float c00 = acc[mi][ni][0] + b0v, c01 = acc[mi][ni][1] + b1v;
            float c10 = acc[mi][ni][2] + b0v, c11 = acc[mi][ni][3] + b1v;
            if (OUT == 0 || OUT == 2) {
                *reinterpret_cast<float2*>(&C[(size_t)row * ldc + col]) = make_float2(c00, c01);
                *reinterpret_cast<float2*>(&C[(size_t)(row + 8) * ldc + col]) = make_float2(c10, c11);
            }
            if (OUT >= 1) {
                __half h0, l0, h1, l1;
                split1(c00, h0, l0); split1(c01, h1, l1);
                *reinterpret_cast<__half2*>(&Ch[(size_t)row * ldc + col]) = __halves2half2(h0, h1);
                *reinterpret_cast<__half2*>(&Cl[(size_t)row * ldc + col]) = __halves2half2(l0, l1);
                split1(c10, h0, l0); split1(c11, h1, l1);
                *reinterpret_cast<__half2*>(&Ch[(size_t)(row + 8) * ldc + col]) = __halves2half2(h0, h1);
                *reinterpret_cast<__half2*>(&Cl[(size_t)(row + 8) * ldc + col]) = __halves2half2(l0, l1);
            }
        }
    }
}

#define SMEM64  (3 * (2 * 64 * ROWB + 2 * 64 * ROWB))      // 61440
#define SMEM128 (3 * (2 * 128 * ROWB + 2 * 128 * ROWB))    // 122880

// ---------------- converts ----------------
__global__ void cvt_split(const float* __restrict__ in, __half* __restrict__ oh,
                          __half* __restrict__ ol, int n)
{
    int i = (blockIdx.x * 256 + threadIdx.x) * 4;
    if (i >= n) return;
    float4 v = *reinterpret_cast<const float4*>(in + i);
    __half h0, l0, h1, l1, h2, l2, h3, l3;
    split1(v.x, h0, l0); split1(v.y, h1, l1); split1(v.z, h2, l2); split1(v.w, h3, l3);
    *reinterpret_cast<__half2*>(oh + i)     = __halves2half2(h0, h1);
    *reinterpret_cast<__half2*>(oh + i + 2) = __halves2half2(h2, h3);
    *reinterpret_cast<__half2*>(ol + i)     = __halves2half2(l0, l1);
    *reinterpret_cast<__half2*>(ol + i + 2) = __halves2half2(l2, l3);
}

// in [R,C] fp32 (row stride ldin) -> oh/ol [C,R] fp16
__global__ void cvt_split_T(const float* __restrict__ in, int ldin,
                            __half* __restrict__ oh, __half* __restrict__ ol,
                            int R, int C)
{
    __shared__ float tile[32][33];
    const int c0 = blockIdx.x * 32, r0 = blockIdx.y * 32;
    const int tx = threadIdx.x, ty = threadIdx.y;
    #pragma unroll
    for (int i = 0; i < 32; i += 8)
        tile[ty + i][tx] = in[(size_t)(r0 + ty + i) * ldin + c0 + tx];
    __syncthreads();
    #pragma unroll
    for (int i = 0; i < 32; i += 8) {
        float v = tile[tx][ty + i];
        __half h, l;
        split1(v, h, l);
        const size_t o = (size_t)(c0 + ty + i) * R + r0 + tx;
        oh[o] = h;
        ol[o] = l;
    }
}

__global__ void pack_bias2(const float* a, const float* b, float* dst) {
    int t = threadIdx.x;
    dst[t] = (t < 256) ? a[t] : b[t - 256];
}
__global__ void pack_bias3(const float* a, const float* b, const float* c, float* dst) {
    int t = threadIdx.x + blockIdx.x * 512;
    dst[t] = (t < 256) ? a[t] : (t < 512 ? b[t - 256] : c[t - 512]);
}

// ---------------- register-resident softmax + fp16 split output ----------------
__global__ void softmax_cvt(const float* __restrict__ Sc, __half* __restrict__ Ph,
                            __half* __restrict__ Pl)
{
    const size_t base = (size_t)blockIdx.x * S;
    const int t = threadIdx.x, lane = t & 31, wid = t >> 5;
    __shared__ float red[8];

    float4 v0 = *reinterpret_cast<const float4*>(Sc + base + t * 4);
    float4 v1 = *reinterpret_cast<const float4*>(Sc + base + 1024 + t * 4);
    float m = fmaxf(fmaxf(fmaxf(v0.x, v0.y), fmaxf(v0.z, v0.w)),
                    fmaxf(fmaxf(v1.x, v1.y), fmaxf(v1.z, v1.w)));
    #pragma unroll
    for (int o = 16; o > 0; o >>= 1) m = fmaxf(m, __shfl_xor_sync(0xffffffffu, m, o));
    if (lane == 0) red[wid] = m;
    __syncthreads();
    m = red[0];
    #pragma unroll
    for (int i = 1; i < 8; i++) m = fmaxf(m, red[i]);
    __syncthreads();

    float e[8];
    e[0] = __expf(v0.x - m); e[1] = __expf(v0.y - m);
    e[2] = __expf(v0.z - m); e[3] = __expf(v0.w - m);
    e[4] = __expf(v1.x - m); e[5] = __expf(v1.y - m);
    e[6] = __expf(v1.z - m); e[7] = __expf(v1.w - m);
    float s = e[0] + e[1] + e[2] + e[3] + e[4] + e[5] + e[6] + e[7];
    #pragma unroll
    for (int o = 16; o > 0; o >>= 1) s += __shfl_xor_sync(0xffffffffu, s, o);
    if (lane == 0) red[wid] = s;
    __syncthreads();
    s = red[0];
    #pragma unroll
    for (int i = 1; i < 8; i++) s += red[i];
    const float inv = 1.0f / s;

    #pragma unroll
    for (int half = 0; half < 2; half++) {
        const size_t o = base + half * 1024 + t * 4;
        __half h0, l0, h1, l1, h2, l2, h3, l3;
        split1(e[half * 4 + 0] * inv, h0, l0);
        split1(e[half * 4 + 1] * inv, h1, l1);
        split1(e[half * 4 + 2] * inv, h2, l2);
        split1(e[half * 4 + 3] * inv, h3, l3);
        *reinterpret_cast<__half2*>(Ph + o)     = __halves2half2(h0, h1);
        *reinterpret_cast<__half2*>(Ph + o + 2) = __halves2half2(h2, h3);
        *reinterpret_cast<__half2*>(Pl + o)     = __halves2half2(l0, l1);
        *reinterpret_cast<__half2*>(Pl + o + 2) = __halves2half2(l2, l3);
    }
}

// ---------------- fp32 softmax (single small row) ----------------
__global__ void softmax_rows(float* __restrict__ Mx, int cols)
{
    float* row = Mx + (size_t)blockIdx.x * cols;
    __shared__ float red[256];
    const int t = threadIdx.x;
    float m = -1e30f;
    for (int c = t; c < cols; c += 256) m = fmaxf(m, row[c]);
    red[t] = m; __syncthreads();
    for (int s = 128; s > 0; s >>= 1) { if (t < s) red[t] = fmaxf(red[t], red[t + s]); __syncthreads(); }
    m = red[0]; __syncthreads();
    float sum = 0.f;
    for (int c = t; c < cols; c += 256) { float e = __expf(row[c] - m); row[c] = e; sum += e; }
    red[t] = sum; __syncthreads();
    for (int s = 128; s > 0; s >>= 1) { if (t < s) red[t] += red[t + s]; __syncthreads(); }
    const float inv = 1.0f / red[0];
    for (int c = t; c < cols; c += 256) row[c] *= inv;
}

// ---------------- row-wise L2 normalize (strided) ----------------
__global__ void l2norm_rows(float* __restrict__ V, int ld, int cols)
{
    float* row = V + (size_t)blockIdx.x * ld;
    __shared__ float red[128];
    const int t = threadIdx.x;
    float s = 0.f;
    for (int c = t; c < cols; c += 128) { float v = row[c]; s += v * v; }
    red[t] = s; __syncthreads();
    for (int st = 64; st > 0; st >>= 1) { if (t < st) red[t] += red[t + st]; __syncthreads(); }
    const float inv = 1.0f / sqrtf(red[0]);
    for (int c = t; c < cols; c += 128) row[c] *= inv;
}

// ---------------- block-3 tiny kernels ----------------
__global__ void rowproj(const float* __restrict__ h, const float* __restrict__ W,
                        const float* __restrict__ b, float* __restrict__ out,
                        int Din, int Nout)
{
    const int n = threadIdx.x;
    if (n >= Nout) return;
    float s = b[n];
    for (int d = 0; d < Din; d++) s = fmaf(h[d], W[(size_t)d * Nout + n], s);
    out[n] = s;
}

__global__ void dotrow(const float* __restrict__ q, const float* __restrict__ Kmat,
                       int ld, float* __restrict__ srow, int Kd)
{
    const int j = blockIdx.x;
    const int t = threadIdx.x;
    float s = 0.f;
    for (int c = t; c < Kd; c += 32) s = fmaf(q[c], Kmat[(size_t)j * ld + c], s);
    #pragma unroll
    for (int o = 16; o > 0; o >>= 1) s += __shfl_down_sync(0xffffffffu, s, o);
    if (t == 0) srow[j] = s;
}

__global__ void zero_out(float* out) { out[threadIdx.x + blockIdx.x * 256] = 0.f; }

// out[d] += sum over a 128-row slice of p[j]*V[j*ld+d]
__global__ void av_row_split(const float* __restrict__ p, const float* __restrict__ V,
                             int ld, float* __restrict__ out)
{
    const int d = blockIdx.x * 256 + threadIdx.x;
    const int j0 = blockIdx.y * 128;
    float s = 0.f;
    #pragma unroll 4
    for (int j = j0; j < j0 + 128; j++) s = fmaf(p[j], V[(size_t)j * ld + d], s);
    atomicAdd(out + d, s);
}

// ---------------- launch ----------------
extern "C" void kernel_launch(void* const* d_in, const int* in_sizes, int n_in,
                              void* d_out, int out_size)
{
    const float* x   = (const float*)d_in[0];   // [8,S,D] — batch 0 only
    const float* Wk1 = (const float*)d_in[1];
    const float* bk1 = (const float*)d_in[2];
    const float* Wq1 = (const float*)d_in[3];
    const float* bq1 = (const float*)d_in[4];
    const float* Wk2 = (const float*)d_in[5];
    const float* bk2 = (const float*)d_in[6];
    const float* Wq2 = (const float*)d_in[7];
    const float* bq2 = (const float*)d_in[8];
    const float* Wv2 = (const float*)d_in[9];
    const float* bv2 = (const float*)d_in[10];
    float* out = (float*)d_out;

    float *sc, *qkv32, *h2, *qrow, *srow, *bqk1, *bqkv2;
    cudaGetSymbolAddress((void**)&sc,    g_sc);
    cudaGetSymbolAddress((void**)&qkv32, g_qkv32);
    cudaGetSymbolAddress((void**)&h2,    g_h2);
    cudaGetSymbolAddress((void**)&qrow,  g_qrow);
    cudaGetSymbolAddress((void**)&srow,  g_srow);
    cudaGetSymbolAddress((void**)&bqk1,  g_bqk1);
    cudaGetSymbolAddress((void**)&bqkv2, g_bqkv2);

    __half *xh, *xl, *xTh, *xTl, *wqk1h, *wqk1l, *wqkv2h, *wqkv2l;
    __half *qk1h, *qk1l, *qkvh, *qkvl, *ph, *pl, *h1h, *h1l, *vTh, *vTl, *h2h, *h2l;
    cudaGetSymbolAddress((void**)&xh, g_xh);   cudaGetSymbolAddress((void**)&xl, g_xl);
    cudaGetSymbolAddress((void**)&xTh, g_xTh); cudaGetSymbolAddress((void**)&xTl, g_xTl);
    cudaGetSymbolAddress((void**)&wqk1h, g_wqk1h);   cudaGetSymbolAddress((void**)&wqk1l, g_wqk1l);
    cudaGetSymbolAddress((void**)&wqkv2h, g_wqkv2h); cudaGetSymbolAddress((void**)&wqkv2l, g_wqkv2l);
    cudaGetSymbolAddress((void**)&qk1h, g_qk1h); cudaGetSymbolAddress((void**)&qk1l, g_qk1l);
    cudaGetSymbolAddress((void**)&qkvh, g_qkvh); cudaGetSymbolAddress((void**)&qkvl, g_qkvl);
    cudaGetSymbolAddress((void**)&ph, g_ph); cudaGetSymbolAddress((void**)&pl, g_pl);
    cudaGetSymbolAddress((void**)&h1h, g_h1h); cudaGetSymbolAddress((void**)&h1l, g_h1l);
    cudaGetSymbolAddress((void**)&vTh, g_vTh); cudaGetSymbolAddress((void**)&vTl, g_vTl);
    cudaGetSymbolAddress((void**)&h2h, g_h2h); cudaGetSymbolAddress((void**)&h2l, g_h2l);

    cudaFuncSetAttribute((const void*)mma_gemm<64, 64, 2, 2, 0>,
                         cudaFuncAttributeMaxDynamicSharedMemorySize, SMEM64);
    cudaFuncSetAttribute((const void*)mma_gemm<64, 64, 2, 2, 1>,
                         cudaFuncAttributeMaxDynamicSharedMemorySize, SMEM64);
    cudaFuncSetAttribute((const void*)mma_gemm<64, 64, 2, 2, 2>,
                         cudaFuncAttributeMaxDynamicSharedMemorySize, SMEM64);
    cudaFuncSetAttribute((const void*)mma_gemm<128, 128, 4, 2, 0>,
                         cudaFuncAttributeMaxDynamicSharedMemorySize, SMEM128);

    const dim3 gP1(512 / 64, S / 64);    // (8,32)  proj1 N=512
    const dim3 gP2(1024 / 64, S / 64);   // (16,32) proj2/3 N=1024
    const dim3 gScor(S / 128, S / 128);  // (16,16)
    const dim3 gAV(D / 64, S / 64);      // (8,32)
    const dim3 tT(32, 8);

    // ---------- Block 1 (launch idx 5 = scores GEMM for ncu) ----------
    cvt_split<<<(S * D) / 1024, 256>>>(x, xh, xl, S * D);                     // 0
    cvt_split_T<<<dim3(KC / 32, D / 32), tT>>>(Wq1, KC, wqk1h, wqk1l, D, KC); // 1
    cvt_split_T<<<dim3(KC / 32, D / 32), tT>>>(Wk1, KC, wqk1h + KC * D, wqk1l + KC * D, D, KC); // 2
    pack_bias2<<<1, 512>>>(bq1, bk1, bqk1);                                   // 3
    mma_gemm<64, 64, 2, 2, 1><<<gP1, 128, SMEM64>>>(xh, xl, wqk1h, wqk1l, bqk1,
        nullptr, qk1h, qk1l, D, D, D, 512);                                   // 4
    mma_gemm<128, 128, 4, 2, 0><<<gScor, 256, SMEM128>>>(qk1h, qk1l, qk1h + 256, qk1l + 256,
        nullptr, sc, nullptr, nullptr, KC, 512, 512, S);                      // 5  <-- ncu
    softmax_cvt<<<S, 256>>>(sc, ph, pl);                                      // 6
    cvt_split_T<<<dim3(D / 32, S / 32), tT>>>(x, D, xTh, xTl, S, D);          // 7
    mma_gemm<64, 64, 2, 2, 1><<<gAV, 128, SMEM64>>>(ph, pl, xTh, xTl, nullptr,
        nullptr, h1h, h1l, S, S, S, D);                                       // 8

    // ---------- Block 2 ----------
    cvt_split_T<<<dim3(KC / 32, D / 32), tT>>>(Wq2, KC, wqkv2h, wqkv2l, D, KC);
    cvt_split_T<<<dim3(KC / 32, D / 32), tT>>>(Wk2, KC, wqkv2h + KC * D, wqkv2l + KC * D, D, KC);
    cvt_split_T<<<dim3(D / 32, D / 32), tT>>>(Wv2, D, wqkv2h + 512 * D, wqkv2l + 512 * D, D, D);
    pack_bias3<<<2, 512>>>(bq2, bk2, bv2, bqkv2);
    mma_gemm<64, 64, 2, 2, 2><<<gP2, 128, SMEM64>>>(h1h, h1l, wqkv2h, wqkv2l, bqkv2,
        qkv32, qkvh, qkvl, D, D, D, 1024);
    l2norm_rows<<<S, 128>>>(qkv32 + 512, 1024, D);
    cvt_split_T<<<dim3(D / 32, S / 32), tT>>>(qkv32 + 512, 1024, vTh, vTl, S, D);
    mma_gemm<128, 128, 4, 2, 0><<<gScor, 256, SMEM128>>>(qkvh, qkvl, qkvh + 256, qkvl + 256,
        nullptr, sc, nullptr, nullptr, KC, 1024, 1024, S);
    softmax_cvt<<<S, 256>>>(sc, ph, pl);
    mma_gemm<64, 64, 2, 2, 2><<<gAV, 128, SMEM64>>>(ph, pl, vTh, vTl, nullptr,
        h2, h2h, h2l, S, S, S, D);

    // ---------- Block 3 (only last query row needed) ----------
    mma_gemm<64, 64, 2, 2, 0><<<gP2, 128, SMEM64>>>(h2h, h2l, wqkv2h, wqkv2l, bqkv2,
        qkv32, nullptr, nullptr, D, D, D, 1024);
    l2norm_rows<<<S, 128>>>(qkv32 + 512, 1024, D);
    rowproj<<<1, KC>>>(h2 + (size_t)(S - 1) * D, Wq2, bq2, qrow, D, KC);
    dotrow<<<S, 32>>>(qrow, qkv32 + 256, 1024, srow, KC);
    softmax_rows<<<1, 256>>>(srow, S);
    zero_out<<<2, 256>>>(out);
    av_row_split<<<dim3(2, 16), 256>>>(srow, qkv32 + 512, 1024, out);
}

// round 7
// speedup vs baseline: 2.6711x; 1.0673x over previous
#include <cuda_runtime.h>
#include <cuda_fp16.h>
#include <cstdint>

// Shapes (fixed)
#define S  2048
#define D  512
#define KC 256

// ---------------- fp32 scratch ----------------
__device__ float g_sc[(size_t)S * S];       // scores
__device__ float g_qkv32[S * 1024];         // packed q|k|v fp32 (blocks 2/3)
__device__ float g_h2[S * D];               // block-2 output fp32
__device__ float g_qrow[KC];
__device__ float g_srow[S];

// ---------------- fp16 hi/lo scratch (16B aligned) ----------------
#define HBUF(name, n) __device__ __align__(16) __half name[n]
HBUF(g_xh,  S * D);   HBUF(g_xl,  S * D);
HBUF(g_xTh, D * S);   HBUF(g_xTl, D * S);
HBUF(g_wqk1h, 512 * D);  HBUF(g_wqk1l, 512 * D);     // [Wq1;Wk1] K-major
HBUF(g_wqkv2h, 1024 * D); HBUF(g_wqkv2l, 1024 * D);  // [Wq2;Wk2;Wv2] K-major
HBUF(g_qk1h, S * 512);  HBUF(g_qk1l, S * 512);
HBUF(g_qkvh, S * 1024); HBUF(g_qkvl, S * 1024);
HBUF(g_ph, (size_t)S * S);  HBUF(g_pl, (size_t)S * S);
HBUF(g_h1h, S * D);  HBUF(g_h1l, S * D);
HBUF(g_vTh, D * S);  HBUF(g_vTl, D * S);
HBUF(g_h2h, S * D);  HBUF(g_h2l, S * D);

// ---------------- helpers ----------------
__device__ __forceinline__ uint32_t smem_u32(const void* p) {
    uint32_t a;
    asm("{ .reg .u64 t; cvta.to.shared.u64 t, %1; cvt.u32.u64 %0, t; }" : "=r"(a) : "l"(p));
    return a;
}
__device__ __forceinline__ void ldsm4(uint32_t* r, uint32_t a) {
    asm volatile("ldmatrix.sync.aligned.m8n8.x4.shared.b16 {%0,%1,%2,%3}, [%4];"
                 : "=r"(r[0]), "=r"(r[1]), "=r"(r[2]), "=r"(r[3]) : "r"(a));
}
__device__ __forceinline__ void mma_f16(float* c, const uint32_t* a, const uint32_t* b) {
    asm volatile(
        "mma.sync.aligned.m16n8k16.row.col.f32.f16.f16.f32 "
        "{%0,%1,%2,%3}, {%4,%5,%6,%7}, {%8,%9}, {%0,%1,%2,%3};"
        : "+f"(c[0]), "+f"(c[1]), "+f"(c[2]), "+f"(c[3])
        : "r"(a[0]), "r"(a[1]), "r"(a[2]), "r"(a[3]), "r"(b[0]), "r"(b[1]));
}
__device__ __forceinline__ void cp16(uint32_t dst, const void* src) {
    asm volatile("cp.async.cg.shared.global [%0], [%1], 16;" :: "r"(dst), "l"(src));
}
#define CP_COMMIT() asm volatile("cp.async.commit_group;" ::: "memory")
#define CP_WAIT1()  asm volatile("cp.async.wait_group 1;" ::: "memory")

__device__ __forceinline__ void split1(float v, __half& h, __half& l) {
    h = __float2half_rn(v);
    l = __float2half_rn(v - __half2float(h));
}

// ---------------- fp16 hi/lo split tensor-core GEMM ----------------
// C[M,N] = (Ah+Al)[M,K] * (Bh+Bl)[N,K]^T + bias.  K-major fp16 operands.
// OUT: 0 = fp32 C; 1 = fp16 Ch/Cl; 2 = both.
// BMODE: 0 none; 1 two-way bias split at col 256; 2 three-way at 256/512.
#define ROWB 80

template <int BM, int BN, int WM, int WN, int OUT, int BMODE>
__global__ void __launch_bounds__(WM* WN * 32, (BM == 64) ? 3 : 1) mma_gemm(
    const __half* __restrict__ Ah, const __half* __restrict__ Al,
    const __half* __restrict__ Bh, const __half* __restrict__ Bl,
    const float* __restrict__ Bi0, const float* __restrict__ Bi1,
    const float* __restrict__ Bi2,
    float* __restrict__ C, __half* __restrict__ Ch, __half* __restrict__ Cl,
    int K, int lda, int ldb, int ldc)
{
    constexpr int T = WM * WN * 32;
    constexpr int WTM = BM / WM, WTN = BN / WN;
    constexpr int MT = WTM / 16, NT = WTN / 8;
    constexpr int ATILE = BM * ROWB;
    constexpr int BTILE = BN * ROWB;
    constexpr int STAGE = 2 * ATILE + 2 * BTILE;

    extern __shared__ char smc[];
    const uint32_t sb0 = smem_u32(smc);
    const int t = threadIdx.x, lane = t & 31, wid = t >> 5;
    const int wm = (wid % WM) * WTM, wn = (wid / WM) * WTN;
    const int m0 = blockIdx.y * BM, n0 = blockIdx.x * BN;

    float acc[MT][NT][4];
    #pragma unroll
    for (int i = 0; i < MT; i++)
        #pragma unroll
        for (int j = 0; j < NT; j++)
            #pragma unroll
            for (int k = 0; k < 4; k++) acc[i][j][k] = 0.f;

    const int NC = K >> 5;

    auto cp_chunk = [&](uint32_t st, int k0) {
        #pragma unroll
        for (int i = 0; i < (BM * 4) / T; i++) {
            int v = t + i * T; int r = v >> 2, s = v & 3;
            uint32_t d = st + (uint32_t)(r * ROWB + s * 16);
            const size_t o = (size_t)(m0 + r) * lda + k0 + s * 8;
            cp16(d, Ah + o);
            cp16(d + ATILE, Al + o);
        }
        #pragma unroll
        for (int i = 0; i < (BN * 4) / T; i++) {
            int v = t + i * T; int r = v >> 2, s = v & 3;
            uint32_t d = st + 2 * ATILE + (uint32_t)(r * ROWB + s * 16);
            const size_t o = (size_t)(n0 + r) * ldb + k0 + s * 8;
            cp16(d, Bh + o);
            cp16(d + BTILE, Bl + o);
        }
    };

    auto mma_stage = [&](uint32_t st) {
        const int l7 = lane & 7, mt = lane >> 3;
        #pragma unroll
        for (int ks = 0; ks < 2; ks++) {
            uint32_t af_h[MT][4], af_l[MT][4];
            #pragma unroll
            for (int mi = 0; mi < MT; mi++) {
                uint32_t ra = st + (uint32_t)((wm + mi * 16 + l7 + ((mt & 1) << 3)) * ROWB
                                              + ks * 32 + ((mt >> 1) << 4));
                ldsm4(af_h[mi], ra);
                ldsm4(af_l[mi], ra + ATILE);
            }
            uint32_t bf_h[NT][2], bf_l[NT][2];
            #pragma unroll
            for (int np = 0; np < NT / 2; np++) {
                uint32_t rb = st + 2 * ATILE
                            + (uint32_t)((wn + np * 16 + ((mt >> 1) << 3) + l7) * ROWB
                                         + ks * 32 + ((mt & 1) << 4));
                uint32_t r4[4];
                ldsm4(r4, rb);
                bf_h[2 * np][0] = r4[0]; bf_h[2 * np][1] = r4[1];
                bf_h[2 * np + 1][0] = r4[2]; bf_h[2 * np + 1][1] = r4[3];
                ldsm4(r4, rb + BTILE);
                bf_l[2 * np][0] = r4[0]; bf_l[2 * np][1] = r4[1];
                bf_l[2 * np + 1][0] = r4[2]; bf_l[2 * np + 1][1] = r4[3];
            }
            #pragma unroll
            for (int mi = 0; mi < MT; mi++)
                #pragma unroll
                for (int ni = 0; ni < NT; ni++) {
                    mma_f16(acc[mi][ni], af_h[mi], bf_h[ni]);
                    mma_f16(acc[mi][ni], af_h[mi], bf_l[ni]);
                    mma_f16(acc[mi][ni], af_l[mi], bf_h[ni]);
                }
        }
    };

    cp_chunk(sb0, 0);
    CP_COMMIT();
    if (NC > 1) cp_chunk(sb0 + STAGE, 32);
    CP_COMMIT();
    for (int c = 0; c < NC; c++) {
        CP_WAIT1();
        __syncthreads();
        mma_stage(sb0 + (uint32_t)((c % 3) * STAGE));
        // NOTE: no barrier needed before prefetch — cp(c+2) writes buffer
        // (c-1)%3, whose readers all passed the barrier at top of iter c.
        if (c + 2 < NC) cp_chunk(sb0 + (uint32_t)(((c + 2) % 3) * STAGE), (c + 2) * 32);
        CP_COMMIT();
    }

    // epilogue
    const int g = lane >> 2, w2 = (lane & 3) * 2;
    #pragma unroll
    for (int ni = 0; ni < NT; ni++) {
        const int col = n0 + wn + ni * 8 + w2;
        float b0v = 0.f, b1v = 0.f;
        if (BMODE == 1) {
            const float* bp = (col < 256) ? Bi0 : (Bi1 - 256);
            b0v = bp[col]; b1v = bp[col + 1];
        } else if (BMODE == 2) {
            const float* bp = (col < 256) ? Bi0 : (col < 512 ? (Bi1 - 256) : (Bi2 - 512));
            b0v = bp[col]; b1v = bp[col + 1];
        }
        #pragma unroll
        for (int mi = 0; mi < MT; mi++) {
            const int row = m0 + wm + mi * 16 + g;
            float c00 = acc[mi][ni][0] + b0v, c01 = acc[mi][ni][1] + b1v;
            float c10 = acc[mi][ni][2] + b0v, c11 = acc[mi][ni][3] + b1v;
            if (OUT == 0 || OUT == 2) {
                *reinterpret_cast<float2*>(&C[(size_t)row * ldc + col]) = make_float2(c00, c01);
                *reinterpret_cast<float2*>(&C[(size_t)(row + 8) * ldc + col]) = make_float2(c10, c11);
            }
            if (OUT >= 1) {
                __half h0, l0, h1, l1;
                split1(c00, h0, l0); split1(c01, h1, l1);
                *reinterpret_cast<__half2*>(&Ch[(size_t)row * ldc + col]) = __halves2half2(h0, h1);
                *reinterpret_cast<__half2*>(&Cl[(size_t)row * ldc + col]) = __halves2half2(l0, l1);
                split1(c10, h0, l0); split1(c11, h1, l1);
                *reinterpret_cast<__half2*>(&Ch[(size_t)(row + 8) * ldc + col]) = __halves2half2(h0, h1);
                *reinterpret_cast<__half2*>(&Cl[(size_t)(row + 8) * ldc + col]) = __halves2half2(l0, l1);
            }
        }
    }
}

#define SMEM64  (3 * (2 * 64 * ROWB + 2 * 64 * ROWB))      // 61440
#define SMEM128 (3 * (2 * 128 * ROWB + 2 * 128 * ROWB))    // 122880

// ---------------- converts ----------------
// in [R,C] fp32 (row stride ldin) -> oh/ol [C,R] fp16 (transposed).
// STRAIGHT: also emit sh/sl [R,C] (dense, stride C).
template <bool STRAIGHT>
__global__ void cvt_split_T(const float* __restrict__ in, int ldin,
                            __half* __restrict__ oh, __half* __restrict__ ol,
                            __half* __restrict__ sh, __half* __restrict__ sl,
                            int R, int C)
{
    __shared__ float tile[32][33];
    const int c0 = blockIdx.x * 32, r0 = blockIdx.y * 32;
    const int tx = threadIdx.x, ty = threadIdx.y;
    #pragma unroll
    for (int i = 0; i < 32; i += 8) {
        float v = in[(size_t)(r0 + ty + i) * ldin + c0 + tx];
        tile[ty + i][tx] = v;
        if (STRAIGHT) {
            __half h, l;
            split1(v, h, l);
            const size_t o = (size_t)(r0 + ty + i) * C + c0 + tx;
            sh[o] = h;
            sl[o] = l;
        }
    }
    __syncthreads();
    #pragma unroll
    for (int i = 0; i < 32; i += 8) {
        float v = tile[tx][ty + i];
        __half h, l;
        split1(v, h, l);
        const size_t o = (size_t)(c0 + ty + i) * R + r0 + tx;
        oh[o] = h;
        ol[o] = l;
    }
}

// Two same-shape weights [R,C] -> transposed hi/lo, dst offset z*C*R (z = blockIdx.z)
__global__ void cvt_T_pair(const float* __restrict__ A, const float* __restrict__ B,
                           __half* __restrict__ oh, __half* __restrict__ ol,
                           int R, int C)
{
    __shared__ float tile[32][33];
    const int z = blockIdx.z;
    const float* in = z ? B : A;
    const size_t zoff = (size_t)z * C * R;
    const int c0 = blockIdx.x * 32, r0 = blockIdx.y * 32;
    const int tx = threadIdx.x, ty = threadIdx.y;
    #pragma unroll
    for (int i = 0; i < 32; i += 8)
        tile[ty + i][tx] = in[(size_t)(r0 + ty + i) * C + c0 + tx];
    __syncthreads();
    #pragma unroll
    for (int i = 0; i < 32; i += 8) {
        float v = tile[tx][ty + i];
        __half h, l;
        split1(v, h, l);
        const size_t o = zoff + (size_t)(c0 + ty + i) * R + r0 + tx;
        oh[o] = h;
        ol[o] = l;
    }
}

// ---------------- register-resident softmax + fp16 split output ----------------
__global__ void softmax_cvt(const float* __restrict__ Sc, __half* __restrict__ Ph,
                            __half* __restrict__ Pl)
{
    const size_t base = (size_t)blockIdx.x * S;
    const int t = threadIdx.x, lane = t & 31, wid = t >> 5;
    __shared__ float red[8];

    float4 v0 = *reinterpret_cast<const float4*>(Sc + base + t * 4);
    float4 v1 = *reinterpret_cast<const float4*>(Sc + base + 1024 + t * 4);
    float m = fmaxf(fmaxf(fmaxf(v0.x, v0.y), fmaxf(v0.z, v0.w)),
                    fmaxf(fmaxf(v1.x, v1.y), fmaxf(v1.z, v1.w)));
    #pragma unroll
    for (int o = 16; o > 0; o >>= 1) m = fmaxf(m, __shfl_xor_sync(0xffffffffu, m, o));
    if (lane == 0) red[wid] = m;
    __syncthreads();
    m = red[0];
    #pragma unroll
    for (int i = 1; i < 8; i++) m = fmaxf(m, red[i]);
    __syncthreads();

    float e[8];
    e[0] = __expf(v0.x - m); e[1] = __expf(v0.y - m);
    e[2] = __expf(v0.z - m); e[3] = __expf(v0.w - m);
    e[4] = __expf(v1.x - m); e[5] = __expf(v1.y - m);
    e[6] = __expf(v1.z - m); e[7] = __expf(v1.w - m);
    float s = e[0] + e[1] + e[2] + e[3] + e[4] + e[5] + e[6] + e[7];
    #pragma unroll
    for (int o = 16; o > 0; o >>= 1) s += __shfl_xor_sync(0xffffffffu, s, o);
    if (lane == 0) red[wid] = s;
    __syncthreads();
    s = red[0];
    #pragma unroll
    for (int i = 1; i < 8; i++) s += red[i];
    const float inv = 1.0f / s;

    #pragma unroll
    for (int half = 0; half < 2; half++) {
        const size_t o = base + half * 1024 + t * 4;
        __half h0, l0, h1, l1, h2, l2, h3, l3;
        split1(e[half * 4 + 0] * inv, h0, l0);
        split1(e[half * 4 + 1] * inv, h1, l1);
        split1(e[half * 4 + 2] * inv, h2, l2);
        split1(e[half * 4 + 3] * inv, h3, l3);
        *reinterpret_cast<__half2*>(Ph + o)     = __halves2half2(h0, h1);
        *reinterpret_cast<__half2*>(Ph + o + 2) = __halves2half2(h2, h3);
        *reinterpret_cast<__half2*>(Pl + o)     = __halves2half2(l0, l1);
        *reinterpret_cast<__half2*>(Pl + o + 2) = __halves2half2(l2, l3);
    }
}

// ---------------- row-wise L2 normalize (strided) ----------------
__global__ void l2norm_rows(float* __restrict__ V, int ld, int cols)
{
    float* row = V + (size_t)blockIdx.x * ld;
    __shared__ float red[128];
    const int t = threadIdx.x;
    float s = 0.f;
    for (int c = t; c < cols; c += 128) { float v = row[c]; s += v * v; }
    red[t] = s; __syncthreads();
    for (int st = 64; st > 0; st >>= 1) { if (t < st) red[t] += red[t + st]; __syncthreads(); }
    const float inv = 1.0f / sqrtf(red[0]);
    for (int c = t; c < cols; c += 128) row[c] *= inv;
}

// ---------------- block-3 tail ----------------
__global__ void rowproj(const float* __restrict__ h, const float* __restrict__ W,
                        const float* __restrict__ b, float* __restrict__ out,
                        int Din, int Nout)
{
    const int n = threadIdx.x;
    if (n >= Nout) return;
    float s = b[n];
    for (int d = 0; d < Din; d++) s = fmaf(h[d], W[(size_t)d * Nout + n], s);
    out[n] = s;
}

__global__ void dotrow(const float* __restrict__ q, const float* __restrict__ Kmat,
                       int ld, float* __restrict__ srow, int Kd)
{
    const int j = blockIdx.x;
    const int t = threadIdx.x;
    float s = 0.f;
    for (int c = t; c < Kd; c += 32) s = fmaf(q[c], Kmat[(size_t)j * ld + c], s);
    #pragma unroll
    for (int o = 16; o > 0; o >>= 1) s += __shfl_down_sync(0xffffffffu, s, o);
    if (t == 0) srow[j] = s;
}

__global__ void zero_out(float* out) { out[threadIdx.x + blockIdx.x * 256] = 0.f; }

// fused softmax (redundant per block) + slice-AV with atomic reduce
__global__ void av_split(const float* __restrict__ srow, const float* __restrict__ V,
                         int ld, float* __restrict__ out)
{
    __shared__ float probs[S];
    __shared__ float red[8];
    const int t = threadIdx.x, lane = t & 31, wid = t >> 5;

    float v[8];
    #pragma unroll
    for (int i = 0; i < 8; i++) v[i] = srow[t + i * 256];
    float m = v[0];
    #pragma unroll
    for (int i = 1; i < 8; i++) m = fmaxf(m, v[i]);
    #pragma unroll
    for (int o = 16; o > 0; o >>= 1) m = fmaxf(m, __shfl_xor_sync(0xffffffffu, m, o));
    if (lane == 0) red[wid] = m;
    __syncthreads();
    m = red[0];
    #pragma unroll
    for (int i = 1; i < 8; i++) m = fmaxf(m, red[i]);
    __syncthreads();

    float s = 0.f;
    #pragma unroll
    for (int i = 0; i < 8; i++) {
        float e = __expf(v[i] - m);
        probs[t + i * 256] = e;
        s += e;
    }
    #pragma unroll
    for (int o = 16; o > 0; o >>= 1) s += __shfl_xor_sync(0xffffffffu, s, o);
    if (lane == 0) red[wid] = s;
    __syncthreads();
    s = red[0];
    #pragma unroll
    for (int i = 1; i < 8; i++) s += red[i];
    const float inv = 1.0f / s;
    __syncthreads();

    const int d = blockIdx.x * 256 + t;
    const int j0 = blockIdx.y * 128;
    float acc = 0.f;
    #pragma unroll 4
    for (int j = j0; j < j0 + 128; j++)
        acc = fmaf(probs[j], V[(size_t)j * ld + d], acc);
    atomicAdd(out + d, acc * inv);
}

// ---------------- launch ----------------
extern "C" void kernel_launch(void* const* d_in, const int* in_sizes, int n_in,
                              void* d_out, int out_size)
{
    const float* x   = (const float*)d_in[0];   // [8,S,D] — batch 0 only
    const float* Wk1 = (const float*)d_in[1];
    const float* bk1 = (const float*)d_in[2];
    const float* Wq1 = (const float*)d_in[3];
    const float* bq1 = (const float*)d_in[4];
    const float* Wk2 = (const float*)d_in[5];
    const float* bk2 = (const float*)d_in[6];
    const float* Wq2 = (const float*)d_in[7];
    const float* bq2 = (const float*)d_in[8];
    const float* Wv2 = (const float*)d_in[9];
    const float* bv2 = (const float*)d_in[10];
    float* out = (float*)d_out;

    float *sc, *qkv32, *h2, *qrow, *srow;
    cudaGetSymbolAddress((void**)&sc,    g_sc);
    cudaGetSymbolAddress((void**)&qkv32, g_qkv32);
    cudaGetSymbolAddress((void**)&h2,    g_h2);
    cudaGetSymbolAddress((void**)&qrow,  g_qrow);
    cudaGetSymbolAddress((void**)&srow,  g_srow);

    __half *xh, *xl, *xTh, *xTl, *wqk1h, *wqk1l, *wqkv2h, *wqkv2l;
    __half *qk1h, *qk1l, *qkvh, *qkvl, *ph, *pl, *h1h, *h1l, *vTh, *vTl, *h2h, *h2l;
    cudaGetSymbolAddress((void**)&xh, g_xh);   cudaGetSymbolAddress((void**)&xl, g_xl);
    cudaGetSymbolAddress((void**)&xTh, g_xTh); cudaGetSymbolAddress((void**)&xTl, g_xTl);
    cudaGetSymbolAddress((void**)&wqk1h, g_wqk1h);   cudaGetSymbolAddress((void**)&wqk1l, g_wqk1l);
    cudaGetSymbolAddress((void**)&wqkv2h, g_wqkv2h); cudaGetSymbolAddress((void**)&wqkv2l, g_wqkv2l);
    cudaGetSymbolAddress((void**)&qk1h, g_qk1h); cudaGetSymbolAddress((void**)&qk1l, g_qk1l);
    cudaGetSymbolAddress((void**)&qkvh, g_qkvh); cudaGetSymbolAddress((void**)&qkvl, g_qkvl);
    cudaGetSymbolAddress((void**)&ph, g_ph); cudaGetSymbolAddress((void**)&pl, g_pl);
    cudaGetSymbolAddress((void**)&h1h, g_h1h); cudaGetSymbolAddress((void**)&h1l, g_h1l);
    cudaGetSymbolAddress((void**)&vTh, g_vTh); cudaGetSymbolAddress((void**)&vTl, g_vTl);
    cudaGetSymbolAddress((void**)&h2h, g_h2h); cudaGetSymbolAddress((void**)&h2l, g_h2l);

    cudaFuncSetAttribute((const void*)mma_gemm<64, 64, 2, 2, 1, 1>,
                         cudaFuncAttributeMaxDynamicSharedMemorySize, SMEM64);
    cudaFuncSetAttribute((const void*)mma_gemm<64, 64, 2, 2, 1, 0>,
                         cudaFuncAttributeMaxDynamicSharedMemorySize, SMEM64);
    cudaFuncSetAttribute((const void*)mma_gemm<64, 64, 2, 2, 2, 2>,
                         cudaFuncAttributeMaxDynamicSharedMemorySize, SMEM64);
    cudaFuncSetAttribute((const void*)mma_gemm<64, 64, 2, 2, 2, 0>,
                         cudaFuncAttributeMaxDynamicSharedMemorySize, SMEM64);
    cudaFuncSetAttribute((const void*)mma_gemm<64, 64, 2, 2, 0, 2>,
                         cudaFuncAttributeMaxDynamicSharedMemorySize, SMEM64);
    cudaFuncSetAttribute((const void*)mma_gemm<128, 128, 4, 2, 0, 0>,
                         cudaFuncAttributeMaxDynamicSharedMemorySize, SMEM128);

    const dim3 gP1(512 / 64, S / 64);    // (8,32)
    const dim3 gP2(1024 / 64, S / 64);   // (16,32)
    const dim3 gScor(S / 128, S / 128);  // (16,16)
    const dim3 gAV(D / 64, S / 64);      // (8,32)
    const dim3 tT(32, 8);

    // ---------- Block 1 ----------
    cvt_split_T<true><<<dim3(D / 32, S / 32), tT>>>(x, D, xTh, xTl, xh, xl, S, D);        // 0
    cvt_T_pair<<<dim3(KC / 32, D / 32, 2), tT>>>(Wq1, Wk1, wqk1h, wqk1l, D, KC);          // 1
    mma_gemm<64, 64, 2, 2, 1, 1><<<gP1, 128, SMEM64>>>(xh, xl, wqk1h, wqk1l,
        bq1, bk1, nullptr, nullptr, qk1h, qk1l, D, D, D, 512);                            // 2
    mma_gemm<128, 128, 4, 2, 0, 0><<<gScor, 256, SMEM128>>>(qk1h, qk1l, qk1h + 256, qk1l + 256,
        nullptr, nullptr, nullptr, sc, nullptr, nullptr, KC, 512, 512, S);                // 3
    softmax_cvt<<<S, 256>>>(sc, ph, pl);                                                  // 4
    mma_gemm<64, 64, 2, 2, 1, 0><<<gAV, 128, SMEM64>>>(ph, pl, xTh, xTl,
        nullptr, nullptr, nullptr, nullptr, h1h, h1l, S, S, S, D);                        // 5

    // ---------- Block 2 ----------
    cvt_T_pair<<<dim3(KC / 32, D / 32, 2), tT>>>(Wq2, Wk2, wqkv2h, wqkv2l, D, KC);
    cvt_split_T<false><<<dim3(D / 32, D / 32), tT>>>(Wv2, D, wqkv2h + 512 * D, wqkv2l + 512 * D,
        nullptr, nullptr, D, D);
    mma_gemm<64, 64, 2, 2, 2, 2><<<gP2, 128, SMEM64>>>(h1h, h1l, wqkv2h, wqkv2l,
        bq2, bk2, bv2, qkv32, qkvh, qkvl, D, D, D, 1024);
    l2norm_rows<<<S, 128>>>(qkv32 + 512, 1024, D);
    cvt_split_T<false><<<dim3(D / 32, S / 32), tT>>>(qkv32 + 512, 1024, vTh, vTl,
        nullptr, nullptr, S, D);
    mma_gemm<128, 128, 4, 2, 0, 0><<<gScor, 256, SMEM128>>>(qkvh, qkvl, qkvh + 256, qkvl + 256,
        nullptr, nullptr, nullptr, sc, nullptr, nullptr, KC, 1024, 1024, S);
    softmax_cvt<<<S, 256>>>(sc, ph, pl);
    mma_gemm<64, 64, 2, 2, 2, 0><<<gAV, 128, SMEM64>>>(ph, pl, vTh, vTl,
        nullptr, nullptr, nullptr, h2, h2h, h2l, S, S, S, D);

    // ---------- Block 3 (only last query row needed) ----------
    mma_gemm<64, 64, 2, 2, 0, 2><<<gP2, 128, SMEM64>>>(h2h, h2l, wqkv2h, wqkv2l,
        bq2, bk2, bv2, qkv32, nullptr, nullptr, D, D, D, 1024);
    l2norm_rows<<<S, 128>>>(qkv32 + 512, 1024, D);
    rowproj<<<1, KC>>>(h2 + (size_t)(S - 1) * D, Wq2, bq2, qrow, D, KC);
    dotrow<<<S, 32>>>(qrow, qkv32 + 256, 1024, srow, KC);
    zero_out<<<2, 256>>>(out);
    av_split<<<dim3(2, 16), 256>>>(srow, qkv32 + 512, 1024, out);
}